// round 11
// baseline (speedup 1.0000x reference)
#include <cuda_runtime.h>
#include <cuda_bf16.h>
#include <math.h>

#define L_LAYERS 3
#define D_DIM    128
#define A_DIM    64
#define NREL     401
#define N_NODE   100000
#define N_EDGE   600000
#define NQ_C     512
#define N_DELTA  731
#define MAX_OUT  (512*50000)

// bf16x2-packed planes, stride 68 words (64 k-pairs + pad, mod32=4)
#define AST 68
#define SMEM_MMA ((128 + 128 + 64 + 64) * AST * 4)   // 104448 B -> 2 CTAs/SM
#define SMEM_GG  ((128 + 128 + 32 + 32) * AST * 4)   // 87040 B  -> 2 CTAs/SM

// ---------------- static device scratch ----------------
__device__ float g_hprev  [N_NODE * D_DIM];
__device__ float g_hidden1[N_NODE * D_DIM];
__device__ float g_agg    [N_NODE * D_DIM];
__device__ float g_gh     [N_NODE * 3 * D_DIM];
__device__ float g_HS     [N_NODE * A_DIM];
__device__ float g_Rattn  [NREL * A_DIM];
__device__ float g_Qattn  [NQ_C * A_DIM];
__device__ float g_Hattn  [N_DELTA * A_DIM];
__device__ float g_Hmsg   [N_DELTA * D_DIM];
__device__ int   g_winner [MAX_OUT];

__device__ __forceinline__ float sigmoidf_(float x) { return 1.0f / (1.0f + expf(-x)); }

// pack two fp32 into one bf16x2 word: low half = x0, high half = x1
__device__ __forceinline__ unsigned pack_bf2(float x0, float x1) {
    unsigned r;
    asm("cvt.rn.bf16x2.f32 %0, %1, %2;" : "=r"(r) : "f"(x1), "f"(x0));
    return r;
}
__device__ __forceinline__ void split_pair(float x0, float x1, unsigned& h, unsigned& l) {
    h = pack_bf2(x0, x1);
    float h0 = __uint_as_float(h << 16);
    float h1 = __uint_as_float(h & 0xFFFF0000u);
    l = pack_bf2(x0 - h0, x1 - h1);
}

__device__ __forceinline__ void mma_bf16(float* c,
                                         unsigned a0, unsigned a1, unsigned a2, unsigned a3,
                                         unsigned b0, unsigned b1) {
    asm volatile(
        "mma.sync.aligned.m16n8k16.row.col.f32.bf16.bf16.f32 "
        "{%0,%1,%2,%3}, {%4,%5,%6,%7}, {%8,%9}, {%0,%1,%2,%3};"
        : "+f"(c[0]), "+f"(c[1]), "+f"(c[2]), "+f"(c[3])
        : "r"(a0), "r"(a1), "r"(a2), "r"(a3), "r"(b0), "r"(b1));
}

__device__ __forceinline__ void ldsm_x4(unsigned& r0, unsigned& r1,
                                        unsigned& r2, unsigned& r3, unsigned addr) {
    asm volatile("ldmatrix.sync.aligned.m8n8.x4.shared.b16 {%0,%1,%2,%3}, [%4];"
                 : "=r"(r0), "=r"(r1), "=r"(r2), "=r"(r3) : "r"(addr));
}

// ---------------- per-relation / per-query attention tables ----------------
__global__ void k_tab_rq(const float* __restrict__ rela_l,
                         const float* __restrict__ Wr_l,
                         const float* __restrict__ Wqr_w_l,
                         const float* __restrict__ Wqr_b_l,
                         const int*   __restrict__ q_rel,
                         float* __restrict__ Rattn,
                         float* __restrict__ Qattn)
{
    __shared__ float hv[128];
    int b = blockIdx.x;
    int a = threadIdx.x; // 0..63
    const float* src = (b < NREL) ? (rela_l + (size_t)b * 128)
                                  : (rela_l + (size_t)q_rel[b - NREL] * 128);
    hv[a] = src[a];
    hv[a + 64] = src[a + 64];
    __syncthreads();
    const float* W = ((b < NREL) ? Wr_l : Wqr_w_l) + (size_t)a * 128;
    float s = 0.f;
#pragma unroll
    for (int k = 0; k < 128; k += 4) {
        float4 w = *(const float4*)(W + k);
        s += hv[k] * w.x + hv[k + 1] * w.y + hv[k + 2] * w.z + hv[k + 3] * w.w;
    }
    if (b < NREL) Rattn[b * 64 + a] = s;
    else          Qattn[(b - NREL) * 64 + a] = s + Wqr_b_l[a];
}

// ---------------- per-delta tables ----------------
__global__ void k_tab_delta(const float* __restrict__ wt1, const float* __restrict__ bt1,
                            const float* __restrict__ wt2, const float* __restrict__ bt2,
                            const float* __restrict__ Wtau_l,
                            float* __restrict__ Hmsg, float* __restrict__ Hattn)
{
    __shared__ float hh[128];
    int di = blockIdx.x;           // 0..730
    float delta = (float)(di - 365);
    int d = threadIdx.x;           // 0..127
    float v = wt1[d] * delta + bt1[d] + sinf(wt2[d] * delta + bt2[d]);
    hh[d] = v;
    Hmsg[(size_t)di * 128 + d] = v;
    __syncthreads();
    if (d < 64) {
        const float* W = Wtau_l + (size_t)d * 128;
        float s = 0.f;
#pragma unroll
        for (int k = 0; k < 128; k += 4) {
            float4 w = *(const float4*)(W + k);
            s += hh[k] * w.x + hh[k + 1] * w.y + hh[k + 2] * w.z + hh[k + 3] * w.w;
        }
        Hattn[(size_t)di * 64 + d] = s;
    }
}

// ---------------- edge kernel: one warp per edge ----------------
__global__ void __launch_bounds__(256) k_edge(
    const int* __restrict__ e_sub, const int* __restrict__ e_rel,
    const int* __restrict__ e_obj, const int* __restrict__ e_ridx,
    const int* __restrict__ e_tau, const int* __restrict__ q_tau,
    const float* __restrict__ HS, const float* __restrict__ Rattn,
    const float* __restrict__ Qattn, const float* __restrict__ Hattn,
    const float* __restrict__ Hmsg, const float* __restrict__ hprev,
    const float* __restrict__ rela_l, const float* __restrict__ walpha_w_l,
    const float* __restrict__ walpha_b_l, float* __restrict__ agg, int zero_h)
{
    int e = (int)((blockIdx.x * blockDim.x + threadIdx.x) >> 5);
    int lane = threadIdx.x & 31;
    if (e >= N_EDGE) return;

    int s_ = e_sub[e];
    int r_ = e_rel[e];
    int o_ = e_obj[e];
    int q_ = e_ridx[e];
    int t_ = e_tau[e];
    int tq = q_tau[q_];
    int tau = (t_ >= 0) ? t_ : tq;
    int di = tau - tq + 365;
    di = min(max(di, 0), 730);

    float2 rr2 = ((const float2*)Rattn)[(size_t)r_ * 32 + lane];
    float2 qq2 = ((const float2*)Qattn)[(size_t)q_ * 32 + lane];
    float2 tt2 = ((const float2*)Hattn)[(size_t)di * 32 + lane];
    float ax = rr2.x + qq2.x + tt2.x;
    float ay = rr2.y + qq2.y + tt2.y;
    if (!zero_h) {
        float2 hs2 = ((const float2*)HS)[(size_t)s_ * 32 + lane];
        ax += hs2.x; ay += hs2.y;
    }
    float vx = fmaxf(ax, 0.f);
    float vy = fmaxf(ay, 0.f);
    float2 wa = ((const float2*)walpha_w_l)[lane];
    float acc = vx * wa.x + vy * wa.y;
#pragma unroll
    for (int off = 16; off; off >>= 1) acc += __shfl_xor_sync(0xffffffffu, acc, off);
    float alpha = 1.0f / (1.0f + expf(-(acc + walpha_b_l[0])));

    float4 r4 = ((const float4*)rela_l)[(size_t)r_ * 32 + lane];
    float4 m4 = ((const float4*)Hmsg)  [(size_t)di * 32 + lane];
    float mx = r4.x + m4.x, my = r4.y + m4.y, mz = r4.z + m4.z, mw = r4.w + m4.w;
    if (!zero_h) {
        float4 h4 = ((const float4*)hprev)[(size_t)s_ * 32 + lane];
        mx += h4.x; my += h4.y; mz += h4.z; mw += h4.w;
    }
    mx *= alpha; my *= alpha; mz *= alpha; mw *= alpha;
    float* dst = agg + (size_t)o_ * 128 + lane * 4;
    asm volatile("red.global.add.v4.f32 [%0], {%1,%2,%3,%4};"
                 :: "l"(dst), "f"(mx), "f"(my), "f"(mz), "f"(mw) : "memory");
}

// ---------------- GEMM (R7): bf16 split planes + ldmatrix, two weight segments ----------------
__global__ void __launch_bounds__(256, 2) k_mma(
    const float* __restrict__ A, int M,
    const float* __restrict__ W1, const float* __restrict__ bias1,
    float* __restrict__ C1, int N1, int relu1,
    const float* __restrict__ W2, const float* __restrict__ bias2,
    float* __restrict__ C2, int N2, int relu2)
{
    extern __shared__ unsigned sm[];
    unsigned* Ah = sm;                  // [128][AST]
    unsigned* Al = sm + 128 * AST;
    unsigned* Bh = sm + 256 * AST;      // [64][AST]
    unsigned* Bl = sm + 320 * AST;

    int tid  = threadIdx.x;
    int bm   = blockIdx.x * 128;
    int lane = tid & 31;
    int warp = tid >> 5;
    int wm   = (warp & 3) * 32;
    int wn   = (warp >> 2) * 32;
    int gr   = lane >> 2;
    int tg   = lane & 3;
    int quad = lane >> 3;
    int lrow = lane & 7;

    for (int i = tid; i < 128 * 32; i += 256) {
        int row = i >> 5;
        int c4  = (i & 31) * 4;
        int grow = bm + row;
        float4 v = (grow < M) ? *(const float4*)(A + (size_t)grow * 128 + c4)
                              : make_float4(0.f, 0.f, 0.f, 0.f);
        unsigned h0, l0, h1, l1;
        split_pair(v.x, v.y, h0, l0);
        split_pair(v.z, v.w, h1, l1);
        int p = row * AST + (c4 >> 1);
        Ah[p] = h0; Ah[p + 1] = h1;
        Al[p] = l0; Al[p + 1] = l1;
    }
    __syncthreads();

    unsigned AhU = (unsigned)__cvta_generic_to_shared(Ah);
    unsigned AlU = (unsigned)__cvta_generic_to_shared(Al);
    unsigned BhU = (unsigned)__cvta_generic_to_shared(Bh);
    unsigned BlU = (unsigned)__cvta_generic_to_shared(Bl);
    unsigned aOff = (unsigned)(((wm + (quad & 1) * 8 + lrow) * AST) * 4 + (quad >> 1) * 16);
    unsigned aAd[2][2];
    aAd[0][0] = AhU + aOff;                 aAd[0][1] = AlU + aOff;
    aAd[1][0] = AhU + aOff + 16 * AST * 4;  aAd[1][1] = AlU + aOff + 16 * AST * 4;
    unsigned bOff = (unsigned)(((wn + lane) * AST) * 4);
    unsigned bAdH = BhU + bOff;
    unsigned bAdL = BlU + bOff;

    int Ntot = N1 + N2;
    for (int nb = 0; nb < Ntot; nb += 64) {
        const float* Wseg; const float* bseg; float* Cseg; int nloc, Nseg, reluseg;
        if (nb < N1) { Wseg = W1; bseg = bias1; Cseg = C1; nloc = nb;      Nseg = N1; reluseg = relu1; }
        else         { Wseg = W2; bseg = bias2; Cseg = C2; nloc = nb - N1; Nseg = N2; reluseg = relu2; }

        for (int i = tid; i < 64 * 32; i += 256) {
            int row = i >> 5;
            int c4  = (i & 31) * 4;
            float4 v = *(const float4*)(Wseg + (size_t)(nloc + row) * 128 + c4);
            unsigned h0, l0, h1, l1;
            split_pair(v.x, v.y, h0, l0);
            split_pair(v.z, v.w, h1, l1);
            int p = row * AST + (c4 >> 1);
            Bh[p] = h0; Bh[p + 1] = h1;
            Bl[p] = l0; Bl[p + 1] = l1;
        }
        __syncthreads();

        float acc[2][4][4];
#pragma unroll
        for (int mt = 0; mt < 2; mt++)
#pragma unroll
            for (int nt = 0; nt < 4; nt++)
#pragma unroll
                for (int r = 0; r < 4; r++) acc[mt][nt][r] = 0.f;

#pragma unroll
        for (int it = 0; it < 8; it++) {
            unsigned off = it * 32;
            unsigned ah[2][4], al[2][4];
#pragma unroll
            for (int mt = 0; mt < 2; mt++) {
                ldsm_x4(ah[mt][0], ah[mt][1], ah[mt][2], ah[mt][3], aAd[mt][0] + off);
                ldsm_x4(al[mt][0], al[mt][1], al[mt][2], al[mt][3], aAd[mt][1] + off);
            }
            unsigned bhlo[4], bhhi[4], bllo[4], blhi[4];
            ldsm_x4(bhlo[0], bhlo[1], bhlo[2], bhlo[3], bAdH + off);
            ldsm_x4(bhhi[0], bhhi[1], bhhi[2], bhhi[3], bAdH + off + 16);
            ldsm_x4(bllo[0], bllo[1], bllo[2], bllo[3], bAdL + off);
            ldsm_x4(blhi[0], blhi[1], blhi[2], blhi[3], bAdL + off + 16);
#pragma unroll
            for (int mt = 0; mt < 2; mt++)
#pragma unroll
                for (int nt = 0; nt < 4; nt++) {
                    mma_bf16(acc[mt][nt], ah[mt][0], ah[mt][1], ah[mt][2], ah[mt][3],
                             bhlo[nt], bhhi[nt]);
                    mma_bf16(acc[mt][nt], ah[mt][0], ah[mt][1], ah[mt][2], ah[mt][3],
                             bllo[nt], blhi[nt]);
                    mma_bf16(acc[mt][nt], al[mt][0], al[mt][1], al[mt][2], al[mt][3],
                             bhlo[nt], bhhi[nt]);
                }
        }
        __syncthreads();

#pragma unroll
        for (int mt = 0; mt < 2; mt++) {
#pragma unroll
            for (int nt = 0; nt < 4; nt++) {
                int col = nloc + wn + nt * 8 + 2 * tg;
                float bx = 0.f, by = 0.f;
                if (bseg) { bx = bseg[col]; by = bseg[col + 1]; }
                int row0 = bm + wm + mt * 16 + gr;
                int row1 = row0 + 8;
                float2 v0 = make_float2(acc[mt][nt][0] + bx, acc[mt][nt][1] + by);
                float2 v1 = make_float2(acc[mt][nt][2] + bx, acc[mt][nt][3] + by);
                if (reluseg) {
                    v0.x = fmaxf(v0.x, 0.f); v0.y = fmaxf(v0.y, 0.f);
                    v1.x = fmaxf(v1.x, 0.f); v1.y = fmaxf(v1.y, 0.f);
                }
                if (row0 < M) *(float2*)(Cseg + (size_t)row0 * Nseg + col) = v0;
                if (row1 < M) *(float2*)(Cseg + (size_t)row1 * Nseg + col) = v1;
            }
        }
    }
}

// ---------------- fused gi-GEMM + GRU ----------------
// For each 32-col gate group j: compute i_r, i_z (stashed as bf16x2 in regs),
// then i_n tile and apply the GRU directly, updating h in place.
// gh==nullptr (layer 0) -> gh gates come from bhh broadcast.
__global__ void __launch_bounds__(256, 2) k_gigru(
    const float* __restrict__ A /*hidden1*/, int M,
    const float* __restrict__ Wih_l, const float* __restrict__ bih_l,
    const float* __restrict__ gh, const float* __restrict__ bhh_l,
    float* __restrict__ h /*hprev in-out*/)
{
    extern __shared__ unsigned sm[];
    unsigned* Ah = sm;                  // [128][AST]
    unsigned* Al = sm + 128 * AST;
    unsigned* Bh = sm + 256 * AST;      // [32][AST]
    unsigned* Bl = sm + 288 * AST;

    int tid  = threadIdx.x;
    int bm   = blockIdx.x * 128;
    int lane = tid & 31;
    int warp = tid >> 5;
    int wm   = (warp & 3) * 32;   // 0,32,64,96
    int wn   = (warp >> 2) * 16;  // 0,16
    int gr   = lane >> 2;
    int tg   = lane & 3;
    int quad = lane >> 3;
    int lrow = lane & 7;

    // ---- load + split A (hidden1) tile ----
    for (int i = tid; i < 128 * 32; i += 256) {
        int row = i >> 5;
        int c4  = (i & 31) * 4;
        int grow = bm + row;
        float4 v = (grow < M) ? *(const float4*)(A + (size_t)grow * 128 + c4)
                              : make_float4(0.f, 0.f, 0.f, 0.f);
        unsigned h0, l0, h1, l1;
        split_pair(v.x, v.y, h0, l0);
        split_pair(v.z, v.w, h1, l1);
        int p = row * AST + (c4 >> 1);
        Ah[p] = h0; Ah[p + 1] = h1;
        Al[p] = l0; Al[p + 1] = l1;
    }
    __syncthreads();

    unsigned AhU = (unsigned)__cvta_generic_to_shared(Ah);
    unsigned AlU = (unsigned)__cvta_generic_to_shared(Al);
    unsigned BhU = (unsigned)__cvta_generic_to_shared(Bh);
    unsigned BlU = (unsigned)__cvta_generic_to_shared(Bl);
    unsigned aOff = (unsigned)(((wm + (quad & 1) * 8 + lrow) * AST) * 4 + (quad >> 1) * 16);
    unsigned aAd[2][2];
    aAd[0][0] = AhU + aOff;                 aAd[0][1] = AlU + aOff;
    aAd[1][0] = AhU + aOff + 16 * AST * 4;  aAd[1][1] = AlU + aOff + 16 * AST * 4;
    // B: 32 rows; matrices [r0-7 klo][r8-15 klo][r0-7 khi][r8-15 khi]
    unsigned bOff = (unsigned)(((wn + (quad & 1) * 8 + lrow) * AST) * 4 + (quad >> 1) * 16);
    unsigned bAdH = BhU + bOff;
    unsigned bAdL = BlU + bOff;

    unsigned rstash[2][2][2];   // [mt][nt][rowhalf] bf16x2 of (i_r+b) pairs
    unsigned zstash[2][2][2];

    for (int j = 0; j < 4; j++) {           // gate-col groups of 32
        for (int g = 0; g < 3; g++) {       // r, z, n
            // ---- load + split B tile: Wih rows [128g + 32j .. +32) ----
            __syncthreads();   // previous MMAs done reading B
            const float* Wt = Wih_l + (size_t)(128 * g + 32 * j) * 128;
            for (int i = tid; i < 32 * 32; i += 256) {
                int row = i >> 5;
                int c4  = (i & 31) * 4;
                float4 v = *(const float4*)(Wt + (size_t)row * 128 + c4);
                unsigned h0, l0, h1, l1;
                split_pair(v.x, v.y, h0, l0);
                split_pair(v.z, v.w, h1, l1);
                int p = row * AST + (c4 >> 1);
                Bh[p] = h0; Bh[p + 1] = h1;
                Bl[p] = l0; Bl[p + 1] = l1;
            }
            __syncthreads();

            float acc[2][2][4];
#pragma unroll
            for (int mt = 0; mt < 2; mt++)
#pragma unroll
                for (int nt = 0; nt < 2; nt++)
#pragma unroll
                    for (int r = 0; r < 4; r++) acc[mt][nt][r] = 0.f;

#pragma unroll
            for (int it = 0; it < 8; it++) {
                unsigned off = it * 32;
                unsigned ah[2][4], al[2][4];
#pragma unroll
                for (int mt = 0; mt < 2; mt++) {
                    ldsm_x4(ah[mt][0], ah[mt][1], ah[mt][2], ah[mt][3], aAd[mt][0] + off);
                    ldsm_x4(al[mt][0], al[mt][1], al[mt][2], al[mt][3], aAd[mt][1] + off);
                }
                unsigned bhm[4], blm[4];
                ldsm_x4(bhm[0], bhm[1], bhm[2], bhm[3], bAdH + off);
                ldsm_x4(blm[0], blm[1], blm[2], blm[3], bAdL + off);
#pragma unroll
                for (int mt = 0; mt < 2; mt++)
#pragma unroll
                    for (int nt = 0; nt < 2; nt++) {
                        mma_bf16(acc[mt][nt], ah[mt][0], ah[mt][1], ah[mt][2], ah[mt][3],
                                 bhm[nt], bhm[nt + 2]);
                        mma_bf16(acc[mt][nt], ah[mt][0], ah[mt][1], ah[mt][2], ah[mt][3],
                                 blm[nt], blm[nt + 2]);
                        mma_bf16(acc[mt][nt], al[mt][0], al[mt][1], al[mt][2], al[mt][3],
                                 bhm[nt], bhm[nt + 2]);
                    }
            }

            // bias + stash / GRU
#pragma unroll
            for (int mt = 0; mt < 2; mt++) {
#pragma unroll
                for (int nt = 0; nt < 2; nt++) {
                    int col = 32 * j + wn + nt * 8 + 2 * tg;          // h column
                    float2 b2 = *(const float2*)(bih_l + 128 * g + col);
                    float p0 = acc[mt][nt][0] + b2.x, p1 = acc[mt][nt][1] + b2.y;
                    float p2 = acc[mt][nt][2] + b2.x, p3 = acc[mt][nt][3] + b2.y;
                    if (g == 0) {
                        rstash[mt][nt][0] = pack_bf2(p0, p1);
                        rstash[mt][nt][1] = pack_bf2(p2, p3);
                    } else if (g == 1) {
                        zstash[mt][nt][0] = pack_bf2(p0, p1);
                        zstash[mt][nt][1] = pack_bf2(p2, p3);
                    } else {
                        // GRU for this fragment
#pragma unroll
                        for (int rh = 0; rh < 2; rh++) {
                            int row = bm + wm + mt * 16 + gr + rh * 8;
                            if (row >= M) continue;
                            float inx = (rh == 0) ? p0 : p2;
                            float iny = (rh == 0) ? p1 : p3;
                            unsigned ru = rstash[mt][nt][rh];
                            unsigned zu = zstash[mt][nt][rh];
                            float irx = __uint_as_float(ru << 16);
                            float iry = __uint_as_float(ru & 0xFFFF0000u);
                            float izx = __uint_as_float(zu << 16);
                            float izy = __uint_as_float(zu & 0xFFFF0000u);
                            float2 ghr, ghz, ghn;
                            if (gh) {
                                const float* gp = gh + (size_t)row * 384 + col;
                                ghr = *(const float2*)(gp);
                                ghz = *(const float2*)(gp + 128);
                                ghn = *(const float2*)(gp + 256);
                            } else {
                                ghr = *(const float2*)(bhh_l + col);
                                ghz = *(const float2*)(bhh_l + 128 + col);
                                ghn = *(const float2*)(bhh_l + 256 + col);
                            }
                            float2 h0 = *(const float2*)(h + (size_t)row * 128 + col);
                            float rx = sigmoidf_(irx + ghr.x), ry = sigmoidf_(iry + ghr.y);
                            float zx = sigmoidf_(izx + ghz.x), zy = sigmoidf_(izy + ghz.y);
                            float nx = tanhf(inx + rx * ghn.x);
                            float ny = tanhf(iny + ry * ghn.y);
                            float2 out;
                            out.x = (1.f - zx) * nx + zx * h0.x;
                            out.y = (1.f - zy) * ny + zy * h0.y;
                            *(float2*)(h + (size_t)row * 128 + col) = out;
                        }
                    }
                }
            }
        }
    }
}

// ---------------- output scatter ----------------
__global__ void k_scat1(const int* __restrict__ nb, const int* __restrict__ ne,
                        int* __restrict__ winner, int n_ent)
{
    int n = blockIdx.x * blockDim.x + threadIdx.x;
    if (n >= N_NODE) return;
    size_t slot = (size_t)nb[n] * n_ent + ne[n];
    atomicMax(&winner[slot], n);
}

__global__ void k_scat2(const float* __restrict__ h, const float* __restrict__ Wfinal,
                        const int* __restrict__ nb, const int* __restrict__ ne,
                        const int* __restrict__ winner, float* __restrict__ out, int n_ent)
{
    int n = (int)((blockIdx.x * blockDim.x + threadIdx.x) >> 5);
    int lane = threadIdx.x & 31;
    if (n >= N_NODE) return;
    float4 hv = ((const float4*)h)[(size_t)n * 32 + lane];
    float4 wv = ((const float4*)Wfinal)[lane];
    float s = hv.x * wv.x + hv.y * wv.y + hv.z * wv.z + hv.w * wv.w;
#pragma unroll
    for (int off = 16; off; off >>= 1) s += __shfl_xor_sync(0xffffffffu, s, off);
    if (lane == 0) {
        size_t slot = (size_t)nb[n] * n_ent + ne[n];
        if (winner[slot] == n) out[slot] = s;
    }
}

// ---------------- host launcher ----------------
extern "C" void kernel_launch(void* const* d_in, const int* in_sizes, int n_in,
                              void* d_out, int out_size)
{
    const float* rela     = (const float*)d_in[0];
    const float* Ws       = (const float*)d_in[1];
    const float* Wr       = (const float*)d_in[2];
    const float* Wqr_w    = (const float*)d_in[3];
    const float* Wqr_b    = (const float*)d_in[4];
    const float* Wtau     = (const float*)d_in[5];
    const float* walpha_w = (const float*)d_in[6];
    const float* walpha_b = (const float*)d_in[7];
    const float* Wh       = (const float*)d_in[8];
    const float* wt1      = (const float*)d_in[9];
    const float* bt1      = (const float*)d_in[10];
    const float* wt2      = (const float*)d_in[11];
    const float* bt2      = (const float*)d_in[12];
    const float* Wih      = (const float*)d_in[13];
    const float* Whh      = (const float*)d_in[14];
    const float* bih      = (const float*)d_in[15];
    const float* bhh      = (const float*)d_in[16];
    const float* Wfinal   = (const float*)d_in[17];
    const int*   q_rel    = (const int*)d_in[18];
    const int*   q_tau    = (const int*)d_in[19];
    const int*   e_ridx   = (const int*)d_in[20];
    const int*   e_rel    = (const int*)d_in[21];
    const int*   e_tau    = (const int*)d_in[22];
    const int*   e_sub    = (const int*)d_in[23];
    const int*   e_obj    = (const int*)d_in[24];
    const int*   nb       = (const int*)d_in[25];
    const int*   ne       = (const int*)d_in[26];

    int nq    = in_sizes[18];
    int n_ent = out_size / nq;

    float *hprev, *hidden1, *agg, *gh, *HS, *Rattn, *Qattn, *Hattn, *Hmsg;
    int* winner;
    cudaGetSymbolAddress((void**)&hprev,   g_hprev);
    cudaGetSymbolAddress((void**)&hidden1, g_hidden1);
    cudaGetSymbolAddress((void**)&agg,     g_agg);
    cudaGetSymbolAddress((void**)&gh,      g_gh);
    cudaGetSymbolAddress((void**)&HS,      g_HS);
    cudaGetSymbolAddress((void**)&Rattn,   g_Rattn);
    cudaGetSymbolAddress((void**)&Qattn,   g_Qattn);
    cudaGetSymbolAddress((void**)&Hattn,   g_Hattn);
    cudaGetSymbolAddress((void**)&Hmsg,    g_Hmsg);
    cudaGetSymbolAddress((void**)&winner,  g_winner);

    cudaFuncSetAttribute(k_mma,   cudaFuncAttributeMaxDynamicSharedMemorySize, SMEM_MMA);
    cudaFuncSetAttribute(k_gigru, cudaFuncAttributeMaxDynamicSharedMemorySize, SMEM_GG);

    cudaMemsetAsync(hprev, 0, sizeof(float) * (size_t)N_NODE * D_DIM);

    const int mblocks = (N_NODE + 127) / 128;   // 782

    for (int l = 0; l < L_LAYERS; l++) {
        cudaMemsetAsync(agg, 0, sizeof(float) * (size_t)N_NODE * D_DIM);

        k_tab_rq<<<NREL + NQ_C, 64>>>(rela + (size_t)l * NREL * 128,
                                      Wr + (size_t)l * 64 * 128,
                                      Wqr_w + (size_t)l * 64 * 128,
                                      Wqr_b + (size_t)l * 64,
                                      q_rel, Rattn, Qattn);
        k_tab_delta<<<N_DELTA, 128>>>(wt1 + (size_t)l * 128, bt1 + (size_t)l * 128,
                                      wt2 + (size_t)l * 128, bt2 + (size_t)l * 128,
                                      Wtau + (size_t)l * 64 * 128, Hmsg, Hattn);
        if (l > 0) {
            // shared-A: HS = hprev@Ws^T  and  gh = hprev@Whh^T + bhh
            k_mma<<<mblocks, 256, SMEM_MMA>>>(hprev, N_NODE,
                                              Ws + (size_t)l * 64 * 128, nullptr, HS, 64, 0,
                                              Whh + (size_t)l * 384 * 128,
                                              bhh + (size_t)l * 384, gh, 384, 0);
        }

        k_edge<<<N_EDGE / 8, 256>>>(e_sub + (size_t)l * N_EDGE, e_rel + (size_t)l * N_EDGE,
                                    e_obj + (size_t)l * N_EDGE, e_ridx + (size_t)l * N_EDGE,
                                    e_tau + (size_t)l * N_EDGE, q_tau,
                                    HS, Rattn, Qattn, Hattn, Hmsg, hprev,
                                    rela + (size_t)l * NREL * 128,
                                    walpha_w + (size_t)l * 64, walpha_b + l, agg,
                                    (l == 0) ? 1 : 0);

        // hidden1 = relu(agg @ Wh^T)
        k_mma<<<mblocks, 256, SMEM_MMA>>>(agg, N_NODE,
                                          Wh + (size_t)l * 128 * 128, nullptr, hidden1, 128, 1,
                                          nullptr, nullptr, nullptr, 0, 0);
        // fused gi GEMM + GRU -> hprev updated in place
        k_gigru<<<mblocks, 256, SMEM_GG>>>(hidden1, N_NODE,
                                           Wih + (size_t)l * 384 * 128,
                                           bih + (size_t)l * 384,
                                           (l > 0) ? gh : nullptr,
                                           bhh + (size_t)l * 384, hprev);
    }

    cudaMemsetAsync(d_out, 0, (size_t)out_size * sizeof(float));
    cudaMemsetAsync(winner, 0xFF, (size_t)out_size * sizeof(int));
    k_scat1<<<(N_NODE + 255) / 256, 256>>>(nb, ne, winner, n_ent);
    k_scat2<<<(N_NODE * 32) / 256, 256>>>(hprev, Wfinal, nb, ne, winner, (float*)d_out, n_ent);
}

// round 12
// speedup vs baseline: 1.0091x; 1.0091x over previous
#include <cuda_runtime.h>
#include <cuda_bf16.h>
#include <math.h>

#define L_LAYERS 3
#define D_DIM    128
#define A_DIM    64
#define NREL     401
#define N_NODE   100000
#define N_EDGE   600000
#define NQ_C     512
#define N_DELTA  731
#define MAX_OUT  (512*50000)

// bf16x2-packed planes, stride 68 words (64 k-pairs + pad, mod32=4)
#define AST 68
#define SMEM_MMA  ((128 + 128 + 64 + 64) * AST * 4)             // 104448 B -> 2 CTAs/SM
#define SMEM_WHGI ((128 + 128 + 64 + 64 + 128 + 128) * AST * 4) // 174080 B -> 1 CTA/SM

// ---------------- static device scratch ----------------
__device__ float g_hprev  [N_NODE * D_DIM];
__device__ float g_agg    [N_NODE * D_DIM];
__device__ float g_gi     [N_NODE * 3 * D_DIM];
__device__ float g_gh     [N_NODE * 3 * D_DIM];
__device__ float g_HS     [N_NODE * A_DIM];
__device__ float g_Rattn  [NREL * A_DIM];
__device__ float g_Qattn  [NQ_C * A_DIM];
__device__ float g_Hattn  [N_DELTA * A_DIM];
__device__ float g_Hmsg   [N_DELTA * D_DIM];
__device__ int   g_winner [MAX_OUT];

__device__ __forceinline__ float sigmoidf_(float x) { return 1.0f / (1.0f + expf(-x)); }

// pack two fp32 into one bf16x2 word: low half = x0, high half = x1
__device__ __forceinline__ unsigned pack_bf2(float x0, float x1) {
    unsigned r;
    asm("cvt.rn.bf16x2.f32 %0, %1, %2;" : "=r"(r) : "f"(x1), "f"(x0));
    return r;
}
__device__ __forceinline__ void split_pair(float x0, float x1, unsigned& h, unsigned& l) {
    h = pack_bf2(x0, x1);
    float h0 = __uint_as_float(h << 16);
    float h1 = __uint_as_float(h & 0xFFFF0000u);
    l = pack_bf2(x0 - h0, x1 - h1);
}

__device__ __forceinline__ void mma_bf16(float* c,
                                         unsigned a0, unsigned a1, unsigned a2, unsigned a3,
                                         unsigned b0, unsigned b1) {
    asm volatile(
        "mma.sync.aligned.m16n8k16.row.col.f32.bf16.bf16.f32 "
        "{%0,%1,%2,%3}, {%4,%5,%6,%7}, {%8,%9}, {%0,%1,%2,%3};"
        : "+f"(c[0]), "+f"(c[1]), "+f"(c[2]), "+f"(c[3])
        : "r"(a0), "r"(a1), "r"(a2), "r"(a3), "r"(b0), "r"(b1));
}

__device__ __forceinline__ void ldsm_x4(unsigned& r0, unsigned& r1,
                                        unsigned& r2, unsigned& r3, unsigned addr) {
    asm volatile("ldmatrix.sync.aligned.m8n8.x4.shared.b16 {%0,%1,%2,%3}, [%4];"
                 : "=r"(r0), "=r"(r1), "=r"(r2), "=r"(r3) : "r"(addr));
}

// ---------------- per-relation / per-query attention tables ----------------
__global__ void k_tab_rq(const float* __restrict__ rela_l,
                         const float* __restrict__ Wr_l,
                         const float* __restrict__ Wqr_w_l,
                         const float* __restrict__ Wqr_b_l,
                         const int*   __restrict__ q_rel,
                         float* __restrict__ Rattn,
                         float* __restrict__ Qattn)
{
    __shared__ float hv[128];
    int b = blockIdx.x;
    int a = threadIdx.x; // 0..63
    const float* src = (b < NREL) ? (rela_l + (size_t)b * 128)
                                  : (rela_l + (size_t)q_rel[b - NREL] * 128);
    hv[a] = src[a];
    hv[a + 64] = src[a + 64];
    __syncthreads();
    const float* W = ((b < NREL) ? Wr_l : Wqr_w_l) + (size_t)a * 128;
    float s = 0.f;
#pragma unroll
    for (int k = 0; k < 128; k += 4) {
        float4 w = *(const float4*)(W + k);
        s += hv[k] * w.x + hv[k + 1] * w.y + hv[k + 2] * w.z + hv[k + 3] * w.w;
    }
    if (b < NREL) Rattn[b * 64 + a] = s;
    else          Qattn[(b - NREL) * 64 + a] = s + Wqr_b_l[a];
}

// ---------------- per-delta tables ----------------
__global__ void k_tab_delta(const float* __restrict__ wt1, const float* __restrict__ bt1,
                            const float* __restrict__ wt2, const float* __restrict__ bt2,
                            const float* __restrict__ Wtau_l,
                            float* __restrict__ Hmsg, float* __restrict__ Hattn)
{
    __shared__ float hh[128];
    int di = blockIdx.x;           // 0..730
    float delta = (float)(di - 365);
    int d = threadIdx.x;           // 0..127
    float v = wt1[d] * delta + bt1[d] + sinf(wt2[d] * delta + bt2[d]);
    hh[d] = v;
    Hmsg[(size_t)di * 128 + d] = v;
    __syncthreads();
    if (d < 64) {
        const float* W = Wtau_l + (size_t)d * 128;
        float s = 0.f;
#pragma unroll
        for (int k = 0; k < 128; k += 4) {
            float4 w = *(const float4*)(W + k);
            s += hh[k] * w.x + hh[k + 1] * w.y + hh[k + 2] * w.z + hh[k + 3] * w.w;
        }
        Hattn[(size_t)di * 64 + d] = s;
    }
}

// ---------------- edge kernel: one warp per edge ----------------
__global__ void __launch_bounds__(256) k_edge(
    const int* __restrict__ e_sub, const int* __restrict__ e_rel,
    const int* __restrict__ e_obj, const int* __restrict__ e_ridx,
    const int* __restrict__ e_tau, const int* __restrict__ q_tau,
    const float* __restrict__ HS, const float* __restrict__ Rattn,
    const float* __restrict__ Qattn, const float* __restrict__ Hattn,
    const float* __restrict__ Hmsg, const float* __restrict__ hprev,
    const float* __restrict__ rela_l, const float* __restrict__ walpha_w_l,
    const float* __restrict__ walpha_b_l, float* __restrict__ agg, int zero_h)
{
    int e = (int)((blockIdx.x * blockDim.x + threadIdx.x) >> 5);
    int lane = threadIdx.x & 31;
    if (e >= N_EDGE) return;

    int s_ = e_sub[e];
    int r_ = e_rel[e];
    int o_ = e_obj[e];
    int q_ = e_ridx[e];
    int t_ = e_tau[e];
    int tq = q_tau[q_];
    int tau = (t_ >= 0) ? t_ : tq;
    int di = tau - tq + 365;
    di = min(max(di, 0), 730);

    float2 rr2 = ((const float2*)Rattn)[(size_t)r_ * 32 + lane];
    float2 qq2 = ((const float2*)Qattn)[(size_t)q_ * 32 + lane];
    float2 tt2 = ((const float2*)Hattn)[(size_t)di * 32 + lane];
    float ax = rr2.x + qq2.x + tt2.x;
    float ay = rr2.y + qq2.y + tt2.y;
    if (!zero_h) {
        float2 hs2 = ((const float2*)HS)[(size_t)s_ * 32 + lane];
        ax += hs2.x; ay += hs2.y;
    }
    float vx = fmaxf(ax, 0.f);
    float vy = fmaxf(ay, 0.f);
    float2 wa = ((const float2*)walpha_w_l)[lane];
    float acc = vx * wa.x + vy * wa.y;
#pragma unroll
    for (int off = 16; off; off >>= 1) acc += __shfl_xor_sync(0xffffffffu, acc, off);
    float alpha = 1.0f / (1.0f + expf(-(acc + walpha_b_l[0])));

    float4 r4 = ((const float4*)rela_l)[(size_t)r_ * 32 + lane];
    float4 m4 = ((const float4*)Hmsg)  [(size_t)di * 32 + lane];
    float mx = r4.x + m4.x, my = r4.y + m4.y, mz = r4.z + m4.z, mw = r4.w + m4.w;
    if (!zero_h) {
        float4 h4 = ((const float4*)hprev)[(size_t)s_ * 32 + lane];
        mx += h4.x; my += h4.y; mz += h4.z; mw += h4.w;
    }
    mx *= alpha; my *= alpha; mz *= alpha; mw *= alpha;
    float* dst = agg + (size_t)o_ * 128 + lane * 4;
    asm volatile("red.global.add.v4.f32 [%0], {%1,%2,%3,%4};"
                 :: "l"(dst), "f"(mx), "f"(my), "f"(mz), "f"(mw) : "memory");
}

// ---------------- GEMM (R7): bf16 split planes + ldmatrix, two weight segments ----------------
__global__ void __launch_bounds__(256, 2) k_mma(
    const float* __restrict__ A, int M,
    const float* __restrict__ W1, const float* __restrict__ bias1,
    float* __restrict__ C1, int N1, int relu1,
    const float* __restrict__ W2, const float* __restrict__ bias2,
    float* __restrict__ C2, int N2, int relu2)
{
    extern __shared__ unsigned sm[];
    unsigned* Ah = sm;                  // [128][AST]
    unsigned* Al = sm + 128 * AST;
    unsigned* Bh = sm + 256 * AST;      // [64][AST]
    unsigned* Bl = sm + 320 * AST;

    int tid  = threadIdx.x;
    int bm   = blockIdx.x * 128;
    int lane = tid & 31;
    int warp = tid >> 5;
    int wm   = (warp & 3) * 32;
    int wn   = (warp >> 2) * 32;
    int gr   = lane >> 2;
    int tg   = lane & 3;
    int quad = lane >> 3;
    int lrow = lane & 7;

    for (int i = tid; i < 128 * 32; i += 256) {
        int row = i >> 5;
        int c4  = (i & 31) * 4;
        int grow = bm + row;
        float4 v = (grow < M) ? *(const float4*)(A + (size_t)grow * 128 + c4)
                              : make_float4(0.f, 0.f, 0.f, 0.f);
        unsigned h0, l0, h1, l1;
        split_pair(v.x, v.y, h0, l0);
        split_pair(v.z, v.w, h1, l1);
        int p = row * AST + (c4 >> 1);
        Ah[p] = h0; Ah[p + 1] = h1;
        Al[p] = l0; Al[p + 1] = l1;
    }
    __syncthreads();

    unsigned AhU = (unsigned)__cvta_generic_to_shared(Ah);
    unsigned AlU = (unsigned)__cvta_generic_to_shared(Al);
    unsigned BhU = (unsigned)__cvta_generic_to_shared(Bh);
    unsigned BlU = (unsigned)__cvta_generic_to_shared(Bl);
    unsigned aOff = (unsigned)(((wm + (quad & 1) * 8 + lrow) * AST) * 4 + (quad >> 1) * 16);
    unsigned aAd[2][2];
    aAd[0][0] = AhU + aOff;                 aAd[0][1] = AlU + aOff;
    aAd[1][0] = AhU + aOff + 16 * AST * 4;  aAd[1][1] = AlU + aOff + 16 * AST * 4;
    unsigned bOff = (unsigned)(((wn + lane) * AST) * 4);
    unsigned bAdH = BhU + bOff;
    unsigned bAdL = BlU + bOff;

    int Ntot = N1 + N2;
    for (int nb = 0; nb < Ntot; nb += 64) {
        const float* Wseg; const float* bseg; float* Cseg; int nloc, Nseg, reluseg;
        if (nb < N1) { Wseg = W1; bseg = bias1; Cseg = C1; nloc = nb;      Nseg = N1; reluseg = relu1; }
        else         { Wseg = W2; bseg = bias2; Cseg = C2; nloc = nb - N1; Nseg = N2; reluseg = relu2; }

        for (int i = tid; i < 64 * 32; i += 256) {
            int row = i >> 5;
            int c4  = (i & 31) * 4;
            float4 v = *(const float4*)(Wseg + (size_t)(nloc + row) * 128 + c4);
            unsigned h0, l0, h1, l1;
            split_pair(v.x, v.y, h0, l0);
            split_pair(v.z, v.w, h1, l1);
            int p = row * AST + (c4 >> 1);
            Bh[p] = h0; Bh[p + 1] = h1;
            Bl[p] = l0; Bl[p + 1] = l1;
        }
        __syncthreads();

        float acc[2][4][4];
#pragma unroll
        for (int mt = 0; mt < 2; mt++)
#pragma unroll
            for (int nt = 0; nt < 4; nt++)
#pragma unroll
                for (int r = 0; r < 4; r++) acc[mt][nt][r] = 0.f;

#pragma unroll
        for (int it = 0; it < 8; it++) {
            unsigned off = it * 32;
            unsigned ah[2][4], al[2][4];
#pragma unroll
            for (int mt = 0; mt < 2; mt++) {
                ldsm_x4(ah[mt][0], ah[mt][1], ah[mt][2], ah[mt][3], aAd[mt][0] + off);
                ldsm_x4(al[mt][0], al[mt][1], al[mt][2], al[mt][3], aAd[mt][1] + off);
            }
            unsigned bhlo[4], bhhi[4], bllo[4], blhi[4];
            ldsm_x4(bhlo[0], bhlo[1], bhlo[2], bhlo[3], bAdH + off);
            ldsm_x4(bhhi[0], bhhi[1], bhhi[2], bhhi[3], bAdH + off + 16);
            ldsm_x4(bllo[0], bllo[1], bllo[2], bllo[3], bAdL + off);
            ldsm_x4(blhi[0], blhi[1], blhi[2], blhi[3], bAdL + off + 16);
#pragma unroll
            for (int mt = 0; mt < 2; mt++)
#pragma unroll
                for (int nt = 0; nt < 4; nt++) {
                    mma_bf16(acc[mt][nt], ah[mt][0], ah[mt][1], ah[mt][2], ah[mt][3],
                             bhlo[nt], bhhi[nt]);
                    mma_bf16(acc[mt][nt], ah[mt][0], ah[mt][1], ah[mt][2], ah[mt][3],
                             bllo[nt], blhi[nt]);
                    mma_bf16(acc[mt][nt], al[mt][0], al[mt][1], al[mt][2], al[mt][3],
                             bhlo[nt], bhhi[nt]);
                }
        }
        __syncthreads();

#pragma unroll
        for (int mt = 0; mt < 2; mt++) {
#pragma unroll
            for (int nt = 0; nt < 4; nt++) {
                int col = nloc + wn + nt * 8 + 2 * tg;
                float bx = 0.f, by = 0.f;
                if (bseg) { bx = bseg[col]; by = bseg[col + 1]; }
                int row0 = bm + wm + mt * 16 + gr;
                int row1 = row0 + 8;
                float2 v0 = make_float2(acc[mt][nt][0] + bx, acc[mt][nt][1] + by);
                float2 v1 = make_float2(acc[mt][nt][2] + bx, acc[mt][nt][3] + by);
                if (reluseg) {
                    v0.x = fmaxf(v0.x, 0.f); v0.y = fmaxf(v0.y, 0.f);
                    v1.x = fmaxf(v1.x, 0.f); v1.y = fmaxf(v1.y, 0.f);
                }
                if (row0 < M) *(float2*)(Cseg + (size_t)row0 * Nseg + col) = v0;
                if (row1 < M) *(float2*)(Cseg + (size_t)row1 * Nseg + col) = v1;
            }
        }
    }
}

// ---------------- fused Wh + gi GEMM: hidden1 lives only in smem ----------------
// Phase 1: hidden1 = relu(agg @ Wh^T)  -> fragments split to bf16 planes A2 in smem
// Phase 2: gi = hidden1 @ Wih^T + bih  -> global (6 n-tiles of 64)
__global__ void __launch_bounds__(256, 1) k_whgi(
    const float* __restrict__ A /*agg*/, int M,
    const float* __restrict__ Wh_l,
    const float* __restrict__ Wih_l, const float* __restrict__ bih_l,
    float* __restrict__ gi)
{
    extern __shared__ unsigned sm[];
    unsigned* A1h = sm;                  // [128][AST]
    unsigned* A1l = sm + 128 * AST;
    unsigned* Bh  = sm + 256 * AST;      // [64][AST]
    unsigned* Bl  = sm + 320 * AST;
    unsigned* A2h = sm + 384 * AST;      // [128][AST]
    unsigned* A2l = sm + 512 * AST;

    int tid  = threadIdx.x;
    int bm   = blockIdx.x * 128;
    int lane = tid & 31;
    int warp = tid >> 5;
    int wm   = (warp & 3) * 32;
    int wn   = (warp >> 2) * 32;
    int gr   = lane >> 2;
    int tg   = lane & 3;
    int quad = lane >> 3;
    int lrow = lane & 7;

    // ---- load + split agg tile into A1 planes ----
    for (int i = tid; i < 128 * 32; i += 256) {
        int row = i >> 5;
        int c4  = (i & 31) * 4;
        int grow = bm + row;
        float4 v = (grow < M) ? *(const float4*)(A + (size_t)grow * 128 + c4)
                              : make_float4(0.f, 0.f, 0.f, 0.f);
        unsigned h0, l0, h1, l1;
        split_pair(v.x, v.y, h0, l0);
        split_pair(v.z, v.w, h1, l1);
        int p = row * AST + (c4 >> 1);
        A1h[p] = h0; A1h[p + 1] = h1;
        A1l[p] = l0; A1l[p + 1] = l1;
    }
    __syncthreads();

    unsigned A1hU = (unsigned)__cvta_generic_to_shared(A1h);
    unsigned A1lU = (unsigned)__cvta_generic_to_shared(A1l);
    unsigned A2hU = (unsigned)__cvta_generic_to_shared(A2h);
    unsigned A2lU = (unsigned)__cvta_generic_to_shared(A2l);
    unsigned BhU  = (unsigned)__cvta_generic_to_shared(Bh);
    unsigned BlU  = (unsigned)__cvta_generic_to_shared(Bl);
    unsigned aOff = (unsigned)(((wm + (quad & 1) * 8 + lrow) * AST) * 4 + (quad >> 1) * 16);
    unsigned a1Ad[2][2], a2Ad[2][2];
    a1Ad[0][0] = A1hU + aOff;                 a1Ad[0][1] = A1lU + aOff;
    a1Ad[1][0] = A1hU + aOff + 16 * AST * 4;  a1Ad[1][1] = A1lU + aOff + 16 * AST * 4;
    a2Ad[0][0] = A2hU + aOff;                 a2Ad[0][1] = A2lU + aOff;
    a2Ad[1][0] = A2hU + aOff + 16 * AST * 4;  a2Ad[1][1] = A2lU + aOff + 16 * AST * 4;
    unsigned bOff = (unsigned)(((wn + lane) * AST) * 4);
    unsigned bAdH = BhU + bOff;
    unsigned bAdL = BlU + bOff;

    // ================= phase 1: hidden1 tiles (Wh, 2 n-tiles) =================
    for (int wt = 0; wt < 2; wt++) {
        const float* Wseg = Wh_l + (size_t)(wt * 64) * 128;
        for (int i = tid; i < 64 * 32; i += 256) {
            int row = i >> 5;
            int c4  = (i & 31) * 4;
            float4 v = *(const float4*)(Wseg + (size_t)row * 128 + c4);
            unsigned h0, l0, h1, l1;
            split_pair(v.x, v.y, h0, l0);
            split_pair(v.z, v.w, h1, l1);
            int p = row * AST + (c4 >> 1);
            Bh[p] = h0; Bh[p + 1] = h1;
            Bl[p] = l0; Bl[p + 1] = l1;
        }
        __syncthreads();

        float acc[2][4][4];
#pragma unroll
        for (int mt = 0; mt < 2; mt++)
#pragma unroll
            for (int nt = 0; nt < 4; nt++)
#pragma unroll
                for (int r = 0; r < 4; r++) acc[mt][nt][r] = 0.f;

#pragma unroll
        for (int it = 0; it < 8; it++) {
            unsigned off = it * 32;
            unsigned ah[2][4], al[2][4];
#pragma unroll
            for (int mt = 0; mt < 2; mt++) {
                ldsm_x4(ah[mt][0], ah[mt][1], ah[mt][2], ah[mt][3], a1Ad[mt][0] + off);
                ldsm_x4(al[mt][0], al[mt][1], al[mt][2], al[mt][3], a1Ad[mt][1] + off);
            }
            unsigned bhlo[4], bhhi[4], bllo[4], blhi[4];
            ldsm_x4(bhlo[0], bhlo[1], bhlo[2], bhlo[3], bAdH + off);
            ldsm_x4(bhhi[0], bhhi[1], bhhi[2], bhhi[3], bAdH + off + 16);
            ldsm_x4(bllo[0], bllo[1], bllo[2], bllo[3], bAdL + off);
            ldsm_x4(blhi[0], blhi[1], blhi[2], blhi[3], bAdL + off + 16);
#pragma unroll
            for (int mt = 0; mt < 2; mt++)
#pragma unroll
                for (int nt = 0; nt < 4; nt++) {
                    mma_bf16(acc[mt][nt], ah[mt][0], ah[mt][1], ah[mt][2], ah[mt][3],
                             bhlo[nt], bhhi[nt]);
                    mma_bf16(acc[mt][nt], ah[mt][0], ah[mt][1], ah[mt][2], ah[mt][3],
                             bllo[nt], blhi[nt]);
                    mma_bf16(acc[mt][nt], al[mt][0], al[mt][1], al[mt][2], al[mt][3],
                             bhlo[nt], bhhi[nt]);
                }
        }
        __syncthreads();   // done reading B before next tile overwrites it

        // relu + split fragments into A2 planes
#pragma unroll
        for (int mt = 0; mt < 2; mt++) {
#pragma unroll
            for (int nt = 0; nt < 4; nt++) {
                int widx = wt * 32 + (wn >> 1) + nt * 4 + tg;  // k-pair index
                int row0 = wm + mt * 16 + gr;
                int row1 = row0 + 8;
                float v0 = fmaxf(acc[mt][nt][0], 0.f);
                float v1 = fmaxf(acc[mt][nt][1], 0.f);
                float v2 = fmaxf(acc[mt][nt][2], 0.f);
                float v3 = fmaxf(acc[mt][nt][3], 0.f);
                unsigned h0, l0, h1, l1;
                split_pair(v0, v1, h0, l0);
                split_pair(v2, v3, h1, l1);
                A2h[row0 * AST + widx] = h0; A2l[row0 * AST + widx] = l0;
                A2h[row1 * AST + widx] = h1; A2l[row1 * AST + widx] = l1;
            }
        }
    }

    // ================= phase 2: gi tiles (Wih, 6 n-tiles) =================
    for (int nb = 0; nb < 384; nb += 64) {
        for (int i = tid; i < 64 * 32; i += 256) {
            int row = i >> 5;
            int c4  = (i & 31) * 4;
            float4 v = *(const float4*)(Wih_l + (size_t)(nb + row) * 128 + c4);
            unsigned h0, l0, h1, l1;
            split_pair(v.x, v.y, h0, l0);
            split_pair(v.z, v.w, h1, l1);
            int p = row * AST + (c4 >> 1);
            Bh[p] = h0; Bh[p + 1] = h1;
            Bl[p] = l0; Bl[p + 1] = l1;
        }
        __syncthreads();   // also orders phase-1 A2 writes before ldmatrix reads

        float acc[2][4][4];
#pragma unroll
        for (int mt = 0; mt < 2; mt++)
#pragma unroll
            for (int nt = 0; nt < 4; nt++)
#pragma unroll
                for (int r = 0; r < 4; r++) acc[mt][nt][r] = 0.f;

#pragma unroll
        for (int it = 0; it < 8; it++) {
            unsigned off = it * 32;
            unsigned ah[2][4], al[2][4];
#pragma unroll
            for (int mt = 0; mt < 2; mt++) {
                ldsm_x4(ah[mt][0], ah[mt][1], ah[mt][2], ah[mt][3], a2Ad[mt][0] + off);
                ldsm_x4(al[mt][0], al[mt][1], al[mt][2], al[mt][3], a2Ad[mt][1] + off);
            }
            unsigned bhlo[4], bhhi[4], bllo[4], blhi[4];
            ldsm_x4(bhlo[0], bhlo[1], bhlo[2], bhlo[3], bAdH + off);
            ldsm_x4(bhhi[0], bhhi[1], bhhi[2], bhhi[3], bAdH + off + 16);
            ldsm_x4(bllo[0], bllo[1], bllo[2], bllo[3], bAdL + off);
            ldsm_x4(blhi[0], blhi[1], blhi[2], blhi[3], bAdL + off + 16);
#pragma unroll
            for (int mt = 0; mt < 2; mt++)
#pragma unroll
                for (int nt = 0; nt < 4; nt++) {
                    mma_bf16(acc[mt][nt], ah[mt][0], ah[mt][1], ah[mt][2], ah[mt][3],
                             bhlo[nt], bhhi[nt]);
                    mma_bf16(acc[mt][nt], ah[mt][0], ah[mt][1], ah[mt][2], ah[mt][3],
                             bllo[nt], blhi[nt]);
                    mma_bf16(acc[mt][nt], al[mt][0], al[mt][1], al[mt][2], al[mt][3],
                             bhlo[nt], bhhi[nt]);
                }
        }
        __syncthreads();

#pragma unroll
        for (int mt = 0; mt < 2; mt++) {
#pragma unroll
            for (int nt = 0; nt < 4; nt++) {
                int col = nb + wn + nt * 8 + 2 * tg;
                float bx = bih_l[col], by = bih_l[col + 1];
                int row0 = bm + wm + mt * 16 + gr;
                int row1 = row0 + 8;
                if (row0 < M)
                    *(float2*)(gi + (size_t)row0 * 384 + col) =
                        make_float2(acc[mt][nt][0] + bx, acc[mt][nt][1] + by);
                if (row1 < M)
                    *(float2*)(gi + (size_t)row1 * 384 + col) =
                        make_float2(acc[mt][nt][2] + bx, acc[mt][nt][3] + by);
            }
        }
    }
}

// ---------------- GRU elementwise; gh==nullptr means hprev was 0 ----------------
__global__ void k_gru(const float* __restrict__ gi, const float* __restrict__ gh,
                      const float* __restrict__ bhh, float* __restrict__ h)
{
    int idx = blockIdx.x * blockDim.x + threadIdx.x;
    if (idx >= N_NODE * 32) return;
    int n = idx >> 5, g = idx & 31;
    const float4* gi4 = (const float4*)(gi + (size_t)n * 384);
    float4 ir = gi4[g], iz = gi4[32 + g], in_ = gi4[64 + g];
    float4 hr, hz, hn;
    if (gh) {
        const float4* gh4 = (const float4*)(gh + (size_t)n * 384);
        hr = gh4[g]; hz = gh4[32 + g]; hn = gh4[64 + g];
    } else {
        const float4* b4 = (const float4*)bhh;
        hr = b4[g]; hz = b4[32 + g]; hn = b4[64 + g];
    }
    float4 h0 = ((const float4*)h)[(size_t)n * 32 + g];
    float4 out;
    {
        float r = sigmoidf_(ir.x + hr.x), z = sigmoidf_(iz.x + hz.x);
        float nn = tanhf(in_.x + r * hn.x);
        out.x = (1.f - z) * nn + z * h0.x;
    }
    {
        float r = sigmoidf_(ir.y + hr.y), z = sigmoidf_(iz.y + hz.y);
        float nn = tanhf(in_.y + r * hn.y);
        out.y = (1.f - z) * nn + z * h0.y;
    }
    {
        float r = sigmoidf_(ir.z + hr.z), z = sigmoidf_(iz.z + hz.z);
        float nn = tanhf(in_.z + r * hn.z);
        out.z = (1.f - z) * nn + z * h0.z;
    }
    {
        float r = sigmoidf_(ir.w + hr.w), z = sigmoidf_(iz.w + hz.w);
        float nn = tanhf(in_.w + r * hn.w);
        out.w = (1.f - z) * nn + z * h0.w;
    }
    ((float4*)h)[(size_t)n * 32 + g] = out;
}

// ---------------- output scatter ----------------
__global__ void k_scat0(const int* __restrict__ nb, const int* __restrict__ ne,
                        int* __restrict__ winner, int n_ent)
{
    int n = blockIdx.x * blockDim.x + threadIdx.x;
    if (n >= N_NODE) return;
    winner[(size_t)nb[n] * n_ent + ne[n]] = -1;
}

__global__ void k_scat1(const int* __restrict__ nb, const int* __restrict__ ne,
                        int* __restrict__ winner, int n_ent)
{
    int n = blockIdx.x * blockDim.x + threadIdx.x;
    if (n >= N_NODE) return;
    size_t slot = (size_t)nb[n] * n_ent + ne[n];
    atomicMax(&winner[slot], n);
}

__global__ void k_scat2(const float* __restrict__ h, const float* __restrict__ Wfinal,
                        const int* __restrict__ nb, const int* __restrict__ ne,
                        const int* __restrict__ winner, float* __restrict__ out, int n_ent)
{
    int n = (int)((blockIdx.x * blockDim.x + threadIdx.x) >> 5);
    int lane = threadIdx.x & 31;
    if (n >= N_NODE) return;
    float4 hv = ((const float4*)h)[(size_t)n * 32 + lane];
    float4 wv = ((const float4*)Wfinal)[lane];
    float s = hv.x * wv.x + hv.y * wv.y + hv.z * wv.z + hv.w * wv.w;
#pragma unroll
    for (int off = 16; off; off >>= 1) s += __shfl_xor_sync(0xffffffffu, s, off);
    if (lane == 0) {
        size_t slot = (size_t)nb[n] * n_ent + ne[n];
        if (winner[slot] == n) out[slot] = s;
    }
}

// ---------------- host launcher ----------------
extern "C" void kernel_launch(void* const* d_in, const int* in_sizes, int n_in,
                              void* d_out, int out_size)
{
    const float* rela     = (const float*)d_in[0];
    const float* Ws       = (const float*)d_in[1];
    const float* Wr       = (const float*)d_in[2];
    const float* Wqr_w    = (const float*)d_in[3];
    const float* Wqr_b    = (const float*)d_in[4];
    const float* Wtau     = (const float*)d_in[5];
    const float* walpha_w = (const float*)d_in[6];
    const float* walpha_b = (const float*)d_in[7];
    const float* Wh       = (const float*)d_in[8];
    const float* wt1      = (const float*)d_in[9];
    const float* bt1      = (const float*)d_in[10];
    const float* wt2      = (const float*)d_in[11];
    const float* bt2      = (const float*)d_in[12];
    const float* Wih      = (const float*)d_in[13];
    const float* Whh      = (const float*)d_in[14];
    const float* bih      = (const float*)d_in[15];
    const float* bhh      = (const float*)d_in[16];
    const float* Wfinal   = (const float*)d_in[17];
    const int*   q_rel    = (const int*)d_in[18];
    const int*   q_tau    = (const int*)d_in[19];
    const int*   e_ridx   = (const int*)d_in[20];
    const int*   e_rel    = (const int*)d_in[21];
    const int*   e_tau    = (const int*)d_in[22];
    const int*   e_sub    = (const int*)d_in[23];
    const int*   e_obj    = (const int*)d_in[24];
    const int*   nb       = (const int*)d_in[25];
    const int*   ne       = (const int*)d_in[26];

    int nq    = in_sizes[18];
    int n_ent = out_size / nq;

    float *hprev, *agg, *gi, *gh, *HS, *Rattn, *Qattn, *Hattn, *Hmsg;
    int* winner;
    cudaGetSymbolAddress((void**)&hprev,   g_hprev);
    cudaGetSymbolAddress((void**)&agg,     g_agg);
    cudaGetSymbolAddress((void**)&gi,      g_gi);
    cudaGetSymbolAddress((void**)&gh,      g_gh);
    cudaGetSymbolAddress((void**)&HS,      g_HS);
    cudaGetSymbolAddress((void**)&Rattn,   g_Rattn);
    cudaGetSymbolAddress((void**)&Qattn,   g_Qattn);
    cudaGetSymbolAddress((void**)&Hattn,   g_Hattn);
    cudaGetSymbolAddress((void**)&Hmsg,    g_Hmsg);
    cudaGetSymbolAddress((void**)&winner,  g_winner);

    cudaFuncSetAttribute(k_mma,  cudaFuncAttributeMaxDynamicSharedMemorySize, SMEM_MMA);
    cudaFuncSetAttribute(k_whgi, cudaFuncAttributeMaxDynamicSharedMemorySize, SMEM_WHGI);

    cudaMemsetAsync(hprev, 0, sizeof(float) * (size_t)N_NODE * D_DIM);

    const int mblocks = (N_NODE + 127) / 128;   // 782

    for (int l = 0; l < L_LAYERS; l++) {
        cudaMemsetAsync(agg, 0, sizeof(float) * (size_t)N_NODE * D_DIM);

        k_tab_rq<<<NREL + NQ_C, 64>>>(rela + (size_t)l * NREL * 128,
                                      Wr + (size_t)l * 64 * 128,
                                      Wqr_w + (size_t)l * 64 * 128,
                                      Wqr_b + (size_t)l * 64,
                                      q_rel, Rattn, Qattn);
        k_tab_delta<<<N_DELTA, 128>>>(wt1 + (size_t)l * 128, bt1 + (size_t)l * 128,
                                      wt2 + (size_t)l * 128, bt2 + (size_t)l * 128,
                                      Wtau + (size_t)l * 64 * 128, Hmsg, Hattn);
        if (l > 0) {
            // shared-A: HS = hprev@Ws^T  and  gh = hprev@Whh^T + bhh
            k_mma<<<mblocks, 256, SMEM_MMA>>>(hprev, N_NODE,
                                              Ws + (size_t)l * 64 * 128, nullptr, HS, 64, 0,
                                              Whh + (size_t)l * 384 * 128,
                                              bhh + (size_t)l * 384, gh, 384, 0);
        }

        k_edge<<<N_EDGE / 8, 256>>>(e_sub + (size_t)l * N_EDGE, e_rel + (size_t)l * N_EDGE,
                                    e_obj + (size_t)l * N_EDGE, e_ridx + (size_t)l * N_EDGE,
                                    e_tau + (size_t)l * N_EDGE, q_tau,
                                    HS, Rattn, Qattn, Hattn, Hmsg, hprev,
                                    rela + (size_t)l * NREL * 128,
                                    walpha_w + (size_t)l * 64, walpha_b + l, agg,
                                    (l == 0) ? 1 : 0);

        // fused: hidden1 = relu(agg@Wh^T) in smem; gi = hidden1@Wih^T + bih
        k_whgi<<<mblocks, 256, SMEM_WHGI>>>(agg, N_NODE,
                                            Wh + (size_t)l * 128 * 128,
                                            Wih + (size_t)l * 384 * 128,
                                            bih + (size_t)l * 384, gi);
        // hprev <- GRU
        k_gru<<<(N_NODE * 32) / 256, 256>>>(gi, (l > 0) ? gh : nullptr,
                                            bhh + (size_t)l * 384, hprev);
    }

    cudaMemsetAsync(d_out, 0, (size_t)out_size * sizeof(float));
    k_scat0<<<(N_NODE + 255) / 256, 256>>>(nb, ne, winner, n_ent);
    k_scat1<<<(N_NODE + 255) / 256, 256>>>(nb, ne, winner, n_ent);
    k_scat2<<<(N_NODE * 32) / 256, 256>>>(hprev, Wfinal, nb, ne, winner, (float*)d_out, n_ent);
}

// round 13
// speedup vs baseline: 1.1038x; 1.0938x over previous
#include <cuda_runtime.h>
#include <cuda_bf16.h>
#include <cuda_fp16.h>
#include <math.h>

#define L_LAYERS 3
#define D_DIM    128
#define A_DIM    64
#define NREL     401
#define N_NODE   100000
#define N_EDGE   600000
#define NQ_C     512
#define N_DELTA  731
#define MAX_OUT  (512*50000)

// bf16x2-packed planes, stride 68 words (64 k-pairs + pad, mod32=4)
#define AST 68
#define SMEM_MMA ((128 + 128 + 64 + 64) * AST * 4)   // 104448 B -> 2 CTAs/SM

// ---------------- static device scratch ----------------
__device__ float  g_hprev  [N_NODE * D_DIM];
__device__ float  g_hidden1[N_NODE * D_DIM];
__device__ float  g_agg    [N_NODE * D_DIM];
__device__ float  g_gi     [N_NODE * 3 * D_DIM];
__device__ float  g_gh     [N_NODE * 3 * D_DIM];
__device__ __half g_HS16   [N_NODE * A_DIM];
__device__ __half g_h16    [N_NODE * D_DIM];
__device__ __half g_Rattn16[NREL * A_DIM];
__device__ __half g_Qattn16[NQ_C * A_DIM];
__device__ __half g_Hattn16[N_DELTA * A_DIM];
__device__ __half g_Hmsg16 [N_DELTA * D_DIM];
__device__ __half g_rela16 [NREL * D_DIM];
__device__ int    g_winner [MAX_OUT];

__device__ __forceinline__ float sigmoidf_(float x) { return 1.0f / (1.0f + expf(-x)); }

__device__ __forceinline__ unsigned pack_bf2(float x0, float x1) {
    unsigned r;
    asm("cvt.rn.bf16x2.f32 %0, %1, %2;" : "=r"(r) : "f"(x1), "f"(x0));
    return r;
}
__device__ __forceinline__ void split_pair(float x0, float x1, unsigned& h, unsigned& l) {
    h = pack_bf2(x0, x1);
    float h0 = __uint_as_float(h << 16);
    float h1 = __uint_as_float(h & 0xFFFF0000u);
    l = pack_bf2(x0 - h0, x1 - h1);
}

__device__ __forceinline__ void mma_bf16(float* c,
                                         unsigned a0, unsigned a1, unsigned a2, unsigned a3,
                                         unsigned b0, unsigned b1) {
    asm volatile(
        "mma.sync.aligned.m16n8k16.row.col.f32.bf16.bf16.f32 "
        "{%0,%1,%2,%3}, {%4,%5,%6,%7}, {%8,%9}, {%0,%1,%2,%3};"
        : "+f"(c[0]), "+f"(c[1]), "+f"(c[2]), "+f"(c[3])
        : "r"(a0), "r"(a1), "r"(a2), "r"(a3), "r"(b0), "r"(b1));
}

__device__ __forceinline__ void ldsm_x4(unsigned& r0, unsigned& r1,
                                        unsigned& r2, unsigned& r3, unsigned addr) {
    asm volatile("ldmatrix.sync.aligned.m8n8.x4.shared.b16 {%0,%1,%2,%3}, [%4];"
                 : "=r"(r0), "=r"(r1), "=r"(r2), "=r"(r3) : "r"(addr));
}

// ---------------- per-relation / per-query attention tables (fp16 out) ----------------
__global__ void k_tab_rq(const float* __restrict__ rela_l,
                         const float* __restrict__ Wr_l,
                         const float* __restrict__ Wqr_w_l,
                         const float* __restrict__ Wqr_b_l,
                         const int*   __restrict__ q_rel,
                         __half* __restrict__ Rattn,
                         __half* __restrict__ Qattn)
{
    __shared__ float hv[128];
    int b = blockIdx.x;
    int a = threadIdx.x; // 0..63
    const float* src = (b < NREL) ? (rela_l + (size_t)b * 128)
                                  : (rela_l + (size_t)q_rel[b - NREL] * 128);
    hv[a] = src[a];
    hv[a + 64] = src[a + 64];
    __syncthreads();
    const float* W = ((b < NREL) ? Wr_l : Wqr_w_l) + (size_t)a * 128;
    float s = 0.f;
#pragma unroll
    for (int k = 0; k < 128; k += 4) {
        float4 w = *(const float4*)(W + k);
        s += hv[k] * w.x + hv[k + 1] * w.y + hv[k + 2] * w.z + hv[k + 3] * w.w;
    }
    if (b < NREL) Rattn[b * 64 + a] = __float2half(s);
    else          Qattn[(b - NREL) * 64 + a] = __float2half(s + Wqr_b_l[a]);
}

// ---------------- per-delta tables (fp16 out) ----------------
__global__ void k_tab_delta(const float* __restrict__ wt1, const float* __restrict__ bt1,
                            const float* __restrict__ wt2, const float* __restrict__ bt2,
                            const float* __restrict__ Wtau_l,
                            __half* __restrict__ Hmsg, __half* __restrict__ Hattn)
{
    __shared__ float hh[128];
    int di = blockIdx.x;           // 0..730
    float delta = (float)(di - 365);
    int d = threadIdx.x;           // 0..127
    float v = wt1[d] * delta + bt1[d] + sinf(wt2[d] * delta + bt2[d]);
    hh[d] = v;
    Hmsg[(size_t)di * 128 + d] = __float2half(v);
    __syncthreads();
    if (d < 64) {
        const float* W = Wtau_l + (size_t)d * 128;
        float s = 0.f;
#pragma unroll
        for (int k = 0; k < 128; k += 4) {
            float4 w = *(const float4*)(W + k);
            s += hh[k] * w.x + hh[k + 1] * w.y + hh[k + 2] * w.z + hh[k + 3] * w.w;
        }
        Hattn[(size_t)di * 64 + d] = __float2half(s);
    }
}

// ---------------- rela fp16 copy for the current layer ----------------
__global__ void k_rel16(const float* __restrict__ rela_l, __half* __restrict__ rela16)
{
    int i = blockIdx.x * blockDim.x + threadIdx.x;
    if (i < NREL * 128) rela16[i] = __float2half(rela_l[i]);
}

// ---------------- edge kernel: one warp per edge, fp16 gathers ----------------
__global__ void __launch_bounds__(256) k_edge(
    const int* __restrict__ e_sub, const int* __restrict__ e_rel,
    const int* __restrict__ e_obj, const int* __restrict__ e_ridx,
    const int* __restrict__ e_tau, const int* __restrict__ q_tau,
    const __half* __restrict__ HS16, const __half* __restrict__ Rattn16,
    const __half* __restrict__ Qattn16, const __half* __restrict__ Hattn16,
    const __half* __restrict__ Hmsg16, const __half* __restrict__ h16,
    const __half* __restrict__ rela16, const float* __restrict__ walpha_w_l,
    const float* __restrict__ walpha_b_l, float* __restrict__ agg, int zero_h)
{
    int e = (int)((blockIdx.x * blockDim.x + threadIdx.x) >> 5);
    int lane = threadIdx.x & 31;
    if (e >= N_EDGE) return;

    int s_ = e_sub[e];
    int r_ = e_rel[e];
    int o_ = e_obj[e];
    int q_ = e_ridx[e];
    int t_ = e_tau[e];
    int tq = q_tau[q_];
    int tau = (t_ >= 0) ? t_ : tq;
    int di = tau - tq + 365;
    di = min(max(di, 0), 730);

    // attention: 64 dims, one half2 per lane per table
    float2 rr2 = __half22float2(((const __half2*)Rattn16)[(size_t)r_ * 32 + lane]);
    float2 qq2 = __half22float2(((const __half2*)Qattn16)[(size_t)q_ * 32 + lane]);
    float2 tt2 = __half22float2(((const __half2*)Hattn16)[(size_t)di * 32 + lane]);
    float ax = rr2.x + qq2.x + tt2.x;
    float ay = rr2.y + qq2.y + tt2.y;
    if (!zero_h) {
        float2 hs2 = __half22float2(((const __half2*)HS16)[(size_t)s_ * 32 + lane]);
        ax += hs2.x; ay += hs2.y;
    }
    float vx = fmaxf(ax, 0.f);
    float vy = fmaxf(ay, 0.f);
    float2 wa = ((const float2*)walpha_w_l)[lane];
    float acc = vx * wa.x + vy * wa.y;
#pragma unroll
    for (int off = 16; off; off >>= 1) acc += __shfl_xor_sync(0xffffffffu, acc, off);
    float alpha = 1.0f / (1.0f + expf(-(acc + walpha_b_l[0])));

    // message: 128 dims, 4 per lane (uint2 = 2x half2)
    uint2 rv = ((const uint2*)(rela16 + (size_t)r_ * 128))[lane];
    uint2 mv = ((const uint2*)(Hmsg16 + (size_t)di * 128))[lane];
    float2 r0 = __half22float2(*(const __half2*)&rv.x);
    float2 r1 = __half22float2(*(const __half2*)&rv.y);
    float2 m0 = __half22float2(*(const __half2*)&mv.x);
    float2 m1 = __half22float2(*(const __half2*)&mv.y);
    float mx = r0.x + m0.x, my = r0.y + m0.y;
    float mz = r1.x + m1.x, mw = r1.y + m1.y;
    if (!zero_h) {
        uint2 hv = ((const uint2*)(h16 + (size_t)s_ * 128))[lane];
        float2 h0 = __half22float2(*(const __half2*)&hv.x);
        float2 h1 = __half22float2(*(const __half2*)&hv.y);
        mx += h0.x; my += h0.y; mz += h1.x; mw += h1.y;
    }
    mx *= alpha; my *= alpha; mz *= alpha; mw *= alpha;
    float* dst = agg + (size_t)o_ * 128 + lane * 4;
    asm volatile("red.global.add.v4.f32 [%0], {%1,%2,%3,%4};"
                 :: "l"(dst), "f"(mx), "f"(my), "f"(mz), "f"(mw) : "memory");
}

// ---------------- GEMM (R7): bf16 split planes + ldmatrix, two weight segments ----------------
// c1half: seg1 output written as fp16 (for HS16).
__global__ void __launch_bounds__(256, 2) k_mma(
    const float* __restrict__ A, int M,
    const float* __restrict__ W1, const float* __restrict__ bias1,
    float* __restrict__ C1, int N1, int relu1,
    const float* __restrict__ W2, const float* __restrict__ bias2,
    float* __restrict__ C2, int N2, int relu2, int c1half)
{
    extern __shared__ unsigned sm[];
    unsigned* Ah = sm;                  // [128][AST]
    unsigned* Al = sm + 128 * AST;
    unsigned* Bh = sm + 256 * AST;      // [64][AST]
    unsigned* Bl = sm + 320 * AST;

    int tid  = threadIdx.x;
    int bm   = blockIdx.x * 128;
    int lane = tid & 31;
    int warp = tid >> 5;
    int wm   = (warp & 3) * 32;
    int wn   = (warp >> 2) * 32;
    int gr   = lane >> 2;
    int tg   = lane & 3;
    int quad = lane >> 3;
    int lrow = lane & 7;

    for (int i = tid; i < 128 * 32; i += 256) {
        int row = i >> 5;
        int c4  = (i & 31) * 4;
        int grow = bm + row;
        float4 v = (grow < M) ? *(const float4*)(A + (size_t)grow * 128 + c4)
                              : make_float4(0.f, 0.f, 0.f, 0.f);
        unsigned h0, l0, h1, l1;
        split_pair(v.x, v.y, h0, l0);
        split_pair(v.z, v.w, h1, l1);
        int p = row * AST + (c4 >> 1);
        Ah[p] = h0; Ah[p + 1] = h1;
        Al[p] = l0; Al[p + 1] = l1;
    }
    __syncthreads();

    unsigned AhU = (unsigned)__cvta_generic_to_shared(Ah);
    unsigned AlU = (unsigned)__cvta_generic_to_shared(Al);
    unsigned BhU = (unsigned)__cvta_generic_to_shared(Bh);
    unsigned BlU = (unsigned)__cvta_generic_to_shared(Bl);
    unsigned aOff = (unsigned)(((wm + (quad & 1) * 8 + lrow) * AST) * 4 + (quad >> 1) * 16);
    unsigned aAd[2][2];
    aAd[0][0] = AhU + aOff;                 aAd[0][1] = AlU + aOff;
    aAd[1][0] = AhU + aOff + 16 * AST * 4;  aAd[1][1] = AlU + aOff + 16 * AST * 4;
    unsigned bOff = (unsigned)(((wn + lane) * AST) * 4);
    unsigned bAdH = BhU + bOff;
    unsigned bAdL = BlU + bOff;

    int Ntot = N1 + N2;
    for (int nb = 0; nb < Ntot; nb += 64) {
        const float* Wseg; const float* bseg; float* Cseg; int nloc, Nseg, reluseg, halfseg;
        if (nb < N1) { Wseg = W1; bseg = bias1; Cseg = C1; nloc = nb;      Nseg = N1; reluseg = relu1; halfseg = c1half; }
        else         { Wseg = W2; bseg = bias2; Cseg = C2; nloc = nb - N1; Nseg = N2; reluseg = relu2; halfseg = 0; }

        for (int i = tid; i < 64 * 32; i += 256) {
            int row = i >> 5;
            int c4  = (i & 31) * 4;
            float4 v = *(const float4*)(Wseg + (size_t)(nloc + row) * 128 + c4);
            unsigned h0, l0, h1, l1;
            split_pair(v.x, v.y, h0, l0);
            split_pair(v.z, v.w, h1, l1);
            int p = row * AST + (c4 >> 1);
            Bh[p] = h0; Bh[p + 1] = h1;
            Bl[p] = l0; Bl[p + 1] = l1;
        }
        __syncthreads();

        float acc[2][4][4];
#pragma unroll
        for (int mt = 0; mt < 2; mt++)
#pragma unroll
            for (int nt = 0; nt < 4; nt++)
#pragma unroll
                for (int r = 0; r < 4; r++) acc[mt][nt][r] = 0.f;

#pragma unroll
        for (int it = 0; it < 8; it++) {
            unsigned off = it * 32;
            unsigned ah[2][4], al[2][4];
#pragma unroll
            for (int mt = 0; mt < 2; mt++) {
                ldsm_x4(ah[mt][0], ah[mt][1], ah[mt][2], ah[mt][3], aAd[mt][0] + off);
                ldsm_x4(al[mt][0], al[mt][1], al[mt][2], al[mt][3], aAd[mt][1] + off);
            }
            unsigned bhlo[4], bhhi[4], bllo[4], blhi[4];
            ldsm_x4(bhlo[0], bhlo[1], bhlo[2], bhlo[3], bAdH + off);
            ldsm_x4(bhhi[0], bhhi[1], bhhi[2], bhhi[3], bAdH + off + 16);
            ldsm_x4(bllo[0], bllo[1], bllo[2], bllo[3], bAdL + off);
            ldsm_x4(blhi[0], blhi[1], blhi[2], blhi[3], bAdL + off + 16);
#pragma unroll
            for (int mt = 0; mt < 2; mt++)
#pragma unroll
                for (int nt = 0; nt < 4; nt++) {
                    mma_bf16(acc[mt][nt], ah[mt][0], ah[mt][1], ah[mt][2], ah[mt][3],
                             bhlo[nt], bhhi[nt]);
                    mma_bf16(acc[mt][nt], ah[mt][0], ah[mt][1], ah[mt][2], ah[mt][3],
                             bllo[nt], blhi[nt]);
                    mma_bf16(acc[mt][nt], al[mt][0], al[mt][1], al[mt][2], al[mt][3],
                             bhlo[nt], bhhi[nt]);
                }
        }
        __syncthreads();

#pragma unroll
        for (int mt = 0; mt < 2; mt++) {
#pragma unroll
            for (int nt = 0; nt < 4; nt++) {
                int col = nloc + wn + nt * 8 + 2 * tg;
                float bx = 0.f, by = 0.f;
                if (bseg) { bx = bseg[col]; by = bseg[col + 1]; }
                int row0 = bm + wm + mt * 16 + gr;
                int row1 = row0 + 8;
                float2 v0 = make_float2(acc[mt][nt][0] + bx, acc[mt][nt][1] + by);
                float2 v1 = make_float2(acc[mt][nt][2] + bx, acc[mt][nt][3] + by);
                if (reluseg) {
                    v0.x = fmaxf(v0.x, 0.f); v0.y = fmaxf(v0.y, 0.f);
                    v1.x = fmaxf(v1.x, 0.f); v1.y = fmaxf(v1.y, 0.f);
                }
                if (halfseg) {
                    __half* Ch = (__half*)Cseg;
                    if (row0 < M) *(__half2*)(Ch + (size_t)row0 * Nseg + col) = __floats2half2_rn(v0.x, v0.y);
                    if (row1 < M) *(__half2*)(Ch + (size_t)row1 * Nseg + col) = __floats2half2_rn(v1.x, v1.y);
                } else {
                    if (row0 < M) *(float2*)(Cseg + (size_t)row0 * Nseg + col) = v0;
                    if (row1 < M) *(float2*)(Cseg + (size_t)row1 * Nseg + col) = v1;
                }
            }
        }
    }
}

// ---------------- GRU elementwise; also emits fp16 shadow of h for edge gathers ----------------
__global__ void k_gru(const float* __restrict__ gi, const float* __restrict__ gh,
                      const float* __restrict__ bhh, float* __restrict__ h,
                      __half* __restrict__ h16)
{
    int idx = blockIdx.x * blockDim.x + threadIdx.x;
    if (idx >= N_NODE * 32) return;
    int n = idx >> 5, g = idx & 31;
    const float4* gi4 = (const float4*)(gi + (size_t)n * 384);
    float4 ir = gi4[g], iz = gi4[32 + g], in_ = gi4[64 + g];
    float4 hr, hz, hn;
    if (gh) {
        const float4* gh4 = (const float4*)(gh + (size_t)n * 384);
        hr = gh4[g]; hz = gh4[32 + g]; hn = gh4[64 + g];
    } else {
        const float4* b4 = (const float4*)bhh;
        hr = b4[g]; hz = b4[32 + g]; hn = b4[64 + g];
    }
    float4 h0 = ((const float4*)h)[(size_t)n * 32 + g];
    float4 out;
    {
        float r = sigmoidf_(ir.x + hr.x), z = sigmoidf_(iz.x + hz.x);
        float nn = tanhf(in_.x + r * hn.x);
        out.x = (1.f - z) * nn + z * h0.x;
    }
    {
        float r = sigmoidf_(ir.y + hr.y), z = sigmoidf_(iz.y + hz.y);
        float nn = tanhf(in_.y + r * hn.y);
        out.y = (1.f - z) * nn + z * h0.y;
    }
    {
        float r = sigmoidf_(ir.z + hr.z), z = sigmoidf_(iz.z + hz.z);
        float nn = tanhf(in_.z + r * hn.z);
        out.z = (1.f - z) * nn + z * h0.z;
    }
    {
        float r = sigmoidf_(ir.w + hr.w), z = sigmoidf_(iz.w + hz.w);
        float nn = tanhf(in_.w + r * hn.w);
        out.w = (1.f - z) * nn + z * h0.w;
    }
    ((float4*)h)[(size_t)n * 32 + g] = out;
    __half2* hp = (__half2*)(h16 + (size_t)n * 128 + g * 4);
    hp[0] = __floats2half2_rn(out.x, out.y);
    hp[1] = __floats2half2_rn(out.z, out.w);
}

// ---------------- output scatter ----------------
__global__ void k_scat0(const int* __restrict__ nb, const int* __restrict__ ne,
                        int* __restrict__ winner, int n_ent)
{
    int n = blockIdx.x * blockDim.x + threadIdx.x;
    if (n >= N_NODE) return;
    winner[(size_t)nb[n] * n_ent + ne[n]] = -1;
}

__global__ void k_scat1(const int* __restrict__ nb, const int* __restrict__ ne,
                        int* __restrict__ winner, int n_ent)
{
    int n = blockIdx.x * blockDim.x + threadIdx.x;
    if (n >= N_NODE) return;
    size_t slot = (size_t)nb[n] * n_ent + ne[n];
    atomicMax(&winner[slot], n);
}

__global__ void k_scat2(const float* __restrict__ h, const float* __restrict__ Wfinal,
                        const int* __restrict__ nb, const int* __restrict__ ne,
                        const int* __restrict__ winner, float* __restrict__ out, int n_ent)
{
    int n = (int)((blockIdx.x * blockDim.x + threadIdx.x) >> 5);
    int lane = threadIdx.x & 31;
    if (n >= N_NODE) return;
    float4 hv = ((const float4*)h)[(size_t)n * 32 + lane];
    float4 wv = ((const float4*)Wfinal)[lane];
    float s = hv.x * wv.x + hv.y * wv.y + hv.z * wv.z + hv.w * wv.w;
#pragma unroll
    for (int off = 16; off; off >>= 1) s += __shfl_xor_sync(0xffffffffu, s, off);
    if (lane == 0) {
        size_t slot = (size_t)nb[n] * n_ent + ne[n];
        if (winner[slot] == n) out[slot] = s;
    }
}

// ---------------- host launcher ----------------
extern "C" void kernel_launch(void* const* d_in, const int* in_sizes, int n_in,
                              void* d_out, int out_size)
{
    const float* rela     = (const float*)d_in[0];
    const float* Ws       = (const float*)d_in[1];
    const float* Wr       = (const float*)d_in[2];
    const float* Wqr_w    = (const float*)d_in[3];
    const float* Wqr_b    = (const float*)d_in[4];
    const float* Wtau     = (const float*)d_in[5];
    const float* walpha_w = (const float*)d_in[6];
    const float* walpha_b = (const float*)d_in[7];
    const float* Wh       = (const float*)d_in[8];
    const float* wt1      = (const float*)d_in[9];
    const float* bt1      = (const float*)d_in[10];
    const float* wt2      = (const float*)d_in[11];
    const float* bt2      = (const float*)d_in[12];
    const float* Wih      = (const float*)d_in[13];
    const float* Whh      = (const float*)d_in[14];
    const float* bih      = (const float*)d_in[15];
    const float* bhh      = (const float*)d_in[16];
    const float* Wfinal   = (const float*)d_in[17];
    const int*   q_rel    = (const int*)d_in[18];
    const int*   q_tau    = (const int*)d_in[19];
    const int*   e_ridx   = (const int*)d_in[20];
    const int*   e_rel    = (const int*)d_in[21];
    const int*   e_tau    = (const int*)d_in[22];
    const int*   e_sub    = (const int*)d_in[23];
    const int*   e_obj    = (const int*)d_in[24];
    const int*   nb       = (const int*)d_in[25];
    const int*   ne       = (const int*)d_in[26];

    int nq    = in_sizes[18];
    int n_ent = out_size / nq;

    float *hprev, *hidden1, *agg, *gi, *gh;
    __half *HS16, *h16, *Rattn16, *Qattn16, *Hattn16, *Hmsg16, *rela16;
    int* winner;
    cudaGetSymbolAddress((void**)&hprev,   g_hprev);
    cudaGetSymbolAddress((void**)&hidden1, g_hidden1);
    cudaGetSymbolAddress((void**)&agg,     g_agg);
    cudaGetSymbolAddress((void**)&gi,      g_gi);
    cudaGetSymbolAddress((void**)&gh,      g_gh);
    cudaGetSymbolAddress((void**)&HS16,    g_HS16);
    cudaGetSymbolAddress((void**)&h16,     g_h16);
    cudaGetSymbolAddress((void**)&Rattn16, g_Rattn16);
    cudaGetSymbolAddress((void**)&Qattn16, g_Qattn16);
    cudaGetSymbolAddress((void**)&Hattn16, g_Hattn16);
    cudaGetSymbolAddress((void**)&Hmsg16,  g_Hmsg16);
    cudaGetSymbolAddress((void**)&rela16,  g_rela16);
    cudaGetSymbolAddress((void**)&winner,  g_winner);

    cudaFuncSetAttribute(k_mma, cudaFuncAttributeMaxDynamicSharedMemorySize, SMEM_MMA);

    cudaMemsetAsync(hprev, 0, sizeof(float) * (size_t)N_NODE * D_DIM);

    const int mblocks = (N_NODE + 127) / 128;   // 782

    for (int l = 0; l < L_LAYERS; l++) {
        cudaMemsetAsync(agg, 0, sizeof(float) * (size_t)N_NODE * D_DIM);

        k_tab_rq<<<NREL + NQ_C, 64>>>(rela + (size_t)l * NREL * 128,
                                      Wr + (size_t)l * 64 * 128,
                                      Wqr_w + (size_t)l * 64 * 128,
                                      Wqr_b + (size_t)l * 64,
                                      q_rel, Rattn16, Qattn16);
        k_tab_delta<<<N_DELTA, 128>>>(wt1 + (size_t)l * 128, bt1 + (size_t)l * 128,
                                      wt2 + (size_t)l * 128, bt2 + (size_t)l * 128,
                                      Wtau + (size_t)l * 64 * 128, Hmsg16, Hattn16);
        k_rel16<<<(NREL * 128 + 255) / 256, 256>>>(rela + (size_t)l * NREL * 128, rela16);

        if (l > 0) {
            // shared-A: HS16 = fp16(hprev@Ws^T)  and  gh = hprev@Whh^T + bhh
            k_mma<<<mblocks, 256, SMEM_MMA>>>(hprev, N_NODE,
                                              Ws + (size_t)l * 64 * 128, nullptr,
                                              (float*)HS16, 64, 0,
                                              Whh + (size_t)l * 384 * 128,
                                              bhh + (size_t)l * 384, gh, 384, 0, 1);
        }

        k_edge<<<N_EDGE / 8, 256>>>(e_sub + (size_t)l * N_EDGE, e_rel + (size_t)l * N_EDGE,
                                    e_obj + (size_t)l * N_EDGE, e_ridx + (size_t)l * N_EDGE,
                                    e_tau + (size_t)l * N_EDGE, q_tau,
                                    HS16, Rattn16, Qattn16, Hattn16, Hmsg16, h16, rela16,
                                    walpha_w + (size_t)l * 64, walpha_b + l, agg,
                                    (l == 0) ? 1 : 0);

        // hidden1 = relu(agg @ Wh^T)
        k_mma<<<mblocks, 256, SMEM_MMA>>>(agg, N_NODE,
                                          Wh + (size_t)l * 128 * 128, nullptr, hidden1, 128, 1,
                                          nullptr, nullptr, nullptr, 0, 0, 0);
        // gi = hidden1 @ Wih^T + bih
        k_mma<<<mblocks, 256, SMEM_MMA>>>(hidden1, N_NODE,
                                          Wih + (size_t)l * 384 * 128,
                                          bih + (size_t)l * 384, gi, 384, 0,
                                          nullptr, nullptr, nullptr, 0, 0, 0);
        // hprev <- GRU (also writes fp16 shadow for next layer's edge gathers)
        k_gru<<<(N_NODE * 32) / 256, 256>>>(gi, (l > 0) ? gh : nullptr,
                                            bhh + (size_t)l * 384, hprev, h16);
    }

    cudaMemsetAsync(d_out, 0, (size_t)out_size * sizeof(float));
    k_scat0<<<(N_NODE + 255) / 256, 256>>>(nb, ne, winner, n_ent);
    k_scat1<<<(N_NODE + 255) / 256, 256>>>(nb, ne, winner, n_ent);
    k_scat2<<<(N_NODE * 32) / 256, 256>>>(hprev, Wfinal, nb, ne, winner, (float*)d_out, n_ent);
}

// round 14
// speedup vs baseline: 1.1326x; 1.0262x over previous
#include <cuda_runtime.h>
#include <cuda_bf16.h>
#include <cuda_fp16.h>
#include <math.h>

#define L_LAYERS 3
#define D_DIM    128
#define A_DIM    64
#define NREL     401
#define N_NODE   100000
#define N_EDGE   600000
#define NQ_C     512
#define N_DELTA  731
#define MAX_OUT  (512*50000)

// bf16x2-packed planes, stride 68 words (64 k-pairs + pad, mod32=4)
#define AST 68
#define SMEM_MMA ((128 + 128 + 64 + 64) * AST * 4)   // 104448 B -> 2 CTAs/SM

// ---------------- static device scratch ----------------
__device__ float  g_hprev  [N_NODE * D_DIM];
__device__ float  g_hidden1[N_NODE * D_DIM];
__device__ float  g_agg    [N_NODE * D_DIM];
__device__ float  g_gi     [N_NODE * 3 * D_DIM];
__device__ float  g_gh     [N_NODE * 3 * D_DIM];
__device__ __half g_HS16   [N_NODE * A_DIM];
__device__ __half g_h16    [N_NODE * D_DIM];
__device__ __half g_Rattn16[NREL * A_DIM];
__device__ __half g_Qattn16[NQ_C * A_DIM];
__device__ __half g_Hattn16[N_DELTA * A_DIM];
__device__ float  g_Hmsg   [N_DELTA * D_DIM];
__device__ int    g_winner [MAX_OUT];

__device__ __forceinline__ float sigmoidf_(float x) { return 1.0f / (1.0f + expf(-x)); }

__device__ __forceinline__ unsigned pack_bf2(float x0, float x1) {
    unsigned r;
    asm("cvt.rn.bf16x2.f32 %0, %1, %2;" : "=r"(r) : "f"(x1), "f"(x0));
    return r;
}
__device__ __forceinline__ void split_pair(float x0, float x1, unsigned& h, unsigned& l) {
    h = pack_bf2(x0, x1);
    float h0 = __uint_as_float(h << 16);
    float h1 = __uint_as_float(h & 0xFFFF0000u);
    l = pack_bf2(x0 - h0, x1 - h1);
}

__device__ __forceinline__ void mma_bf16(float* c,
                                         unsigned a0, unsigned a1, unsigned a2, unsigned a3,
                                         unsigned b0, unsigned b1) {
    asm volatile(
        "mma.sync.aligned.m16n8k16.row.col.f32.bf16.bf16.f32 "
        "{%0,%1,%2,%3}, {%4,%5,%6,%7}, {%8,%9}, {%0,%1,%2,%3};"
        : "+f"(c[0]), "+f"(c[1]), "+f"(c[2]), "+f"(c[3])
        : "r"(a0), "r"(a1), "r"(a2), "r"(a3), "r"(b0), "r"(b1));
}

__device__ __forceinline__ void ldsm_x4(unsigned& r0, unsigned& r1,
                                        unsigned& r2, unsigned& r3, unsigned addr) {
    asm volatile("ldmatrix.sync.aligned.m8n8.x4.shared.b16 {%0,%1,%2,%3}, [%4];"
                 : "=r"(r0), "=r"(r1), "=r"(r2), "=r"(r3) : "r"(addr));
}

// ---------------- per-relation / per-query attention tables (fp16 out) ----------------
__global__ void k_tab_rq(const float* __restrict__ rela_l,
                         const float* __restrict__ Wr_l,
                         const float* __restrict__ Wqr_w_l,
                         const float* __restrict__ Wqr_b_l,
                         const int*   __restrict__ q_rel,
                         __half* __restrict__ Rattn,
                         __half* __restrict__ Qattn)
{
    __shared__ float hv[128];
    int b = blockIdx.x;
    int a = threadIdx.x; // 0..63
    const float* src = (b < NREL) ? (rela_l + (size_t)b * 128)
                                  : (rela_l + (size_t)q_rel[b - NREL] * 128);
    hv[a] = src[a];
    hv[a + 64] = src[a + 64];
    __syncthreads();
    const float* W = ((b < NREL) ? Wr_l : Wqr_w_l) + (size_t)a * 128;
    float s = 0.f;
#pragma unroll
    for (int k = 0; k < 128; k += 4) {
        float4 w = *(const float4*)(W + k);
        s += hv[k] * w.x + hv[k + 1] * w.y + hv[k + 2] * w.z + hv[k + 3] * w.w;
    }
    if (b < NREL) Rattn[b * 64 + a] = __float2half(s);
    else          Qattn[(b - NREL) * 64 + a] = __float2half(s + Wqr_b_l[a]);
}

// ---------------- per-delta tables (Hmsg fp32, Hattn fp16) ----------------
__global__ void k_tab_delta(const float* __restrict__ wt1, const float* __restrict__ bt1,
                            const float* __restrict__ wt2, const float* __restrict__ bt2,
                            const float* __restrict__ Wtau_l,
                            float* __restrict__ Hmsg, __half* __restrict__ Hattn)
{
    __shared__ float hh[128];
    int di = blockIdx.x;           // 0..730
    float delta = (float)(di - 365);
    int d = threadIdx.x;           // 0..127
    float v = wt1[d] * delta + bt1[d] + sinf(wt2[d] * delta + bt2[d]);
    hh[d] = v;
    Hmsg[(size_t)di * 128 + d] = v;
    __syncthreads();
    if (d < 64) {
        const float* W = Wtau_l + (size_t)d * 128;
        float s = 0.f;
#pragma unroll
        for (int k = 0; k < 128; k += 4) {
            float4 w = *(const float4*)(W + k);
            s += hh[k] * w.x + hh[k + 1] * w.y + hh[k + 2] * w.z + hh[k + 3] * w.w;
        }
        Hattn[(size_t)di * 64 + d] = __float2half(s);
    }
}

// ---------------- edge kernel: one warp per edge ----------------
// Attention tables fp16 (half2 sums); message: rela/Hmsg fp32, hs fp16.
__global__ void __launch_bounds__(256) k_edge(
    const int* __restrict__ e_sub, const int* __restrict__ e_rel,
    const int* __restrict__ e_obj, const int* __restrict__ e_ridx,
    const int* __restrict__ e_tau, const int* __restrict__ q_tau,
    const __half* __restrict__ HS16, const __half* __restrict__ Rattn16,
    const __half* __restrict__ Qattn16, const __half* __restrict__ Hattn16,
    const float* __restrict__ Hmsg, const __half* __restrict__ h16,
    const float* __restrict__ rela_l, const float* __restrict__ walpha_w_l,
    const float* __restrict__ walpha_b_l, float* __restrict__ agg, int zero_h)
{
    int e = (int)((blockIdx.x * blockDim.x + threadIdx.x) >> 5);
    int lane = threadIdx.x & 31;
    if (e >= N_EDGE) return;

    int s_ = e_sub[e];
    int r_ = e_rel[e];
    int o_ = e_obj[e];
    int q_ = e_ridx[e];
    int t_ = e_tau[e];
    int tq = q_tau[q_];
    int tau = (t_ >= 0) ? t_ : tq;
    int di = tau - tq + 365;
    di = min(max(di, 0), 730);

    // attention: half2 sums of fp16 tables, one convert at the end
    __half2 ra = ((const __half2*)Rattn16)[(size_t)r_ * 32 + lane];
    __half2 qa = ((const __half2*)Qattn16)[(size_t)q_ * 32 + lane];
    __half2 ta = ((const __half2*)Hattn16)[(size_t)di * 32 + lane];
    __half2 s2 = __hadd2(__hadd2(ra, qa), ta);
    if (!zero_h) {
        __half2 hsa = ((const __half2*)HS16)[(size_t)s_ * 32 + lane];
        s2 = __hadd2(s2, hsa);
    }
    float2 a2 = __half22float2(s2);
    float vx = fmaxf(a2.x, 0.f);
    float vy = fmaxf(a2.y, 0.f);
    float2 wa = ((const float2*)walpha_w_l)[lane];
    float acc = vx * wa.x + vy * wa.y;
#pragma unroll
    for (int off = 16; off; off >>= 1) acc += __shfl_xor_sync(0xffffffffu, acc, off);
    float alpha = 1.0f / (1.0f + expf(-(acc + walpha_b_l[0])));

    // message: fp32 rela + fp32 Hmsg (+ fp16 hs gather)
    float4 r4 = ((const float4*)(rela_l + (size_t)r_ * 128))[lane];
    float4 m4 = ((const float4*)(Hmsg   + (size_t)di * 128))[lane];
    float mx = r4.x + m4.x, my = r4.y + m4.y;
    float mz = r4.z + m4.z, mw = r4.w + m4.w;
    if (!zero_h) {
        uint2 hv = ((const uint2*)(h16 + (size_t)s_ * 128))[lane];
        float2 h0 = __half22float2(*(const __half2*)&hv.x);
        float2 h1 = __half22float2(*(const __half2*)&hv.y);
        mx += h0.x; my += h0.y; mz += h1.x; mw += h1.y;
    }
    mx *= alpha; my *= alpha; mz *= alpha; mw *= alpha;
    float* dst = agg + (size_t)o_ * 128 + lane * 4;
    asm volatile("red.global.add.v4.f32 [%0], {%1,%2,%3,%4};"
                 :: "l"(dst), "f"(mx), "f"(my), "f"(mz), "f"(mw) : "memory");
}

// ---------------- GEMM (R7): bf16 split planes + ldmatrix, two weight segments ----------------
// c1half: seg1 output written as fp16 (for HS16).
__global__ void __launch_bounds__(256, 2) k_mma(
    const float* __restrict__ A, int M,
    const float* __restrict__ W1, const float* __restrict__ bias1,
    float* __restrict__ C1, int N1, int relu1,
    const float* __restrict__ W2, const float* __restrict__ bias2,
    float* __restrict__ C2, int N2, int relu2, int c1half)
{
    extern __shared__ unsigned sm[];
    unsigned* Ah = sm;                  // [128][AST]
    unsigned* Al = sm + 128 * AST;
    unsigned* Bh = sm + 256 * AST;      // [64][AST]
    unsigned* Bl = sm + 320 * AST;

    int tid  = threadIdx.x;
    int bm   = blockIdx.x * 128;
    int lane = tid & 31;
    int warp = tid >> 5;
    int wm   = (warp & 3) * 32;
    int wn   = (warp >> 2) * 32;
    int gr   = lane >> 2;
    int tg   = lane & 3;
    int quad = lane >> 3;
    int lrow = lane & 7;

    for (int i = tid; i < 128 * 32; i += 256) {
        int row = i >> 5;
        int c4  = (i & 31) * 4;
        int grow = bm + row;
        float4 v = (grow < M) ? *(const float4*)(A + (size_t)grow * 128 + c4)
                              : make_float4(0.f, 0.f, 0.f, 0.f);
        unsigned h0, l0, h1, l1;
        split_pair(v.x, v.y, h0, l0);
        split_pair(v.z, v.w, h1, l1);
        int p = row * AST + (c4 >> 1);
        Ah[p] = h0; Ah[p + 1] = h1;
        Al[p] = l0; Al[p + 1] = l1;
    }
    __syncthreads();

    unsigned AhU = (unsigned)__cvta_generic_to_shared(Ah);
    unsigned AlU = (unsigned)__cvta_generic_to_shared(Al);
    unsigned BhU = (unsigned)__cvta_generic_to_shared(Bh);
    unsigned BlU = (unsigned)__cvta_generic_to_shared(Bl);
    unsigned aOff = (unsigned)(((wm + (quad & 1) * 8 + lrow) * AST) * 4 + (quad >> 1) * 16);
    unsigned aAd[2][2];
    aAd[0][0] = AhU + aOff;                 aAd[0][1] = AlU + aOff;
    aAd[1][0] = AhU + aOff + 16 * AST * 4;  aAd[1][1] = AlU + aOff + 16 * AST * 4;
    unsigned bOff = (unsigned)(((wn + lane) * AST) * 4);
    unsigned bAdH = BhU + bOff;
    unsigned bAdL = BlU + bOff;

    int Ntot = N1 + N2;
    for (int nb = 0; nb < Ntot; nb += 64) {
        const float* Wseg; const float* bseg; float* Cseg; int nloc, Nseg, reluseg, halfseg;
        if (nb < N1) { Wseg = W1; bseg = bias1; Cseg = C1; nloc = nb;      Nseg = N1; reluseg = relu1; halfseg = c1half; }
        else         { Wseg = W2; bseg = bias2; Cseg = C2; nloc = nb - N1; Nseg = N2; reluseg = relu2; halfseg = 0; }

        for (int i = tid; i < 64 * 32; i += 256) {
            int row = i >> 5;
            int c4  = (i & 31) * 4;
            float4 v = *(const float4*)(Wseg + (size_t)(nloc + row) * 128 + c4);
            unsigned h0, l0, h1, l1;
            split_pair(v.x, v.y, h0, l0);
            split_pair(v.z, v.w, h1, l1);
            int p = row * AST + (c4 >> 1);
            Bh[p] = h0; Bh[p + 1] = h1;
            Bl[p] = l0; Bl[p + 1] = l1;
        }
        __syncthreads();

        float acc[2][4][4];
#pragma unroll
        for (int mt = 0; mt < 2; mt++)
#pragma unroll
            for (int nt = 0; nt < 4; nt++)
#pragma unroll
                for (int r = 0; r < 4; r++) acc[mt][nt][r] = 0.f;

#pragma unroll
        for (int it = 0; it < 8; it++) {
            unsigned off = it * 32;
            unsigned ah[2][4], al[2][4];
#pragma unroll
            for (int mt = 0; mt < 2; mt++) {
                ldsm_x4(ah[mt][0], ah[mt][1], ah[mt][2], ah[mt][3], aAd[mt][0] + off);
                ldsm_x4(al[mt][0], al[mt][1], al[mt][2], al[mt][3], aAd[mt][1] + off);
            }
            unsigned bhlo[4], bhhi[4], bllo[4], blhi[4];
            ldsm_x4(bhlo[0], bhlo[1], bhlo[2], bhlo[3], bAdH + off);
            ldsm_x4(bhhi[0], bhhi[1], bhhi[2], bhhi[3], bAdH + off + 16);
            ldsm_x4(bllo[0], bllo[1], bllo[2], bllo[3], bAdL + off);
            ldsm_x4(blhi[0], blhi[1], blhi[2], blhi[3], bAdL + off + 16);
#pragma unroll
            for (int mt = 0; mt < 2; mt++)
#pragma unroll
                for (int nt = 0; nt < 4; nt++) {
                    mma_bf16(acc[mt][nt], ah[mt][0], ah[mt][1], ah[mt][2], ah[mt][3],
                             bhlo[nt], bhhi[nt]);
                    mma_bf16(acc[mt][nt], ah[mt][0], ah[mt][1], ah[mt][2], ah[mt][3],
                             bllo[nt], blhi[nt]);
                    mma_bf16(acc[mt][nt], al[mt][0], al[mt][1], al[mt][2], al[mt][3],
                             bhlo[nt], bhhi[nt]);
                }
        }
        __syncthreads();

#pragma unroll
        for (int mt = 0; mt < 2; mt++) {
#pragma unroll
            for (int nt = 0; nt < 4; nt++) {
                int col = nloc + wn + nt * 8 + 2 * tg;
                float bx = 0.f, by = 0.f;
                if (bseg) { bx = bseg[col]; by = bseg[col + 1]; }
                int row0 = bm + wm + mt * 16 + gr;
                int row1 = row0 + 8;
                float2 v0 = make_float2(acc[mt][nt][0] + bx, acc[mt][nt][1] + by);
                float2 v1 = make_float2(acc[mt][nt][2] + bx, acc[mt][nt][3] + by);
                if (reluseg) {
                    v0.x = fmaxf(v0.x, 0.f); v0.y = fmaxf(v0.y, 0.f);
                    v1.x = fmaxf(v1.x, 0.f); v1.y = fmaxf(v1.y, 0.f);
                }
                if (halfseg) {
                    __half* Ch = (__half*)Cseg;
                    if (row0 < M) *(__half2*)(Ch + (size_t)row0 * Nseg + col) = __floats2half2_rn(v0.x, v0.y);
                    if (row1 < M) *(__half2*)(Ch + (size_t)row1 * Nseg + col) = __floats2half2_rn(v1.x, v1.y);
                } else {
                    if (row0 < M) *(float2*)(Cseg + (size_t)row0 * Nseg + col) = v0;
                    if (row1 < M) *(float2*)(Cseg + (size_t)row1 * Nseg + col) = v1;
                }
            }
        }
    }
}

// ---------------- GRU elementwise; also emits fp16 shadow of h for edge gathers ----------------
__global__ void k_gru(const float* __restrict__ gi, const float* __restrict__ gh,
                      const float* __restrict__ bhh, float* __restrict__ h,
                      __half* __restrict__ h16)
{
    int idx = blockIdx.x * blockDim.x + threadIdx.x;
    if (idx >= N_NODE * 32) return;
    int n = idx >> 5, g = idx & 31;
    const float4* gi4 = (const float4*)(gi + (size_t)n * 384);
    float4 ir = gi4[g], iz = gi4[32 + g], in_ = gi4[64 + g];
    float4 hr, hz, hn;
    if (gh) {
        const float4* gh4 = (const float4*)(gh + (size_t)n * 384);
        hr = gh4[g]; hz = gh4[32 + g]; hn = gh4[64 + g];
    } else {
        const float4* b4 = (const float4*)bhh;
        hr = b4[g]; hz = b4[32 + g]; hn = b4[64 + g];
    }
    float4 h0 = ((const float4*)h)[(size_t)n * 32 + g];
    float4 out;
    {
        float r = sigmoidf_(ir.x + hr.x), z = sigmoidf_(iz.x + hz.x);
        float nn = tanhf(in_.x + r * hn.x);
        out.x = (1.f - z) * nn + z * h0.x;
    }
    {
        float r = sigmoidf_(ir.y + hr.y), z = sigmoidf_(iz.y + hz.y);
        float nn = tanhf(in_.y + r * hn.y);
        out.y = (1.f - z) * nn + z * h0.y;
    }
    {
        float r = sigmoidf_(ir.z + hr.z), z = sigmoidf_(iz.z + hz.z);
        float nn = tanhf(in_.z + r * hn.z);
        out.z = (1.f - z) * nn + z * h0.z;
    }
    {
        float r = sigmoidf_(ir.w + hr.w), z = sigmoidf_(iz.w + hz.w);
        float nn = tanhf(in_.w + r * hn.w);
        out.w = (1.f - z) * nn + z * h0.w;
    }
    ((float4*)h)[(size_t)n * 32 + g] = out;
    __half2* hp = (__half2*)(h16 + (size_t)n * 128 + g * 4);
    hp[0] = __floats2half2_rn(out.x, out.y);
    hp[1] = __floats2half2_rn(out.z, out.w);
}

// ---------------- output scatter ----------------
__global__ void k_scat0(const int* __restrict__ nb, const int* __restrict__ ne,
                        int* __restrict__ winner, int n_ent)
{
    int n = blockIdx.x * blockDim.x + threadIdx.x;
    if (n >= N_NODE) return;
    winner[(size_t)nb[n] * n_ent + ne[n]] = -1;
}

__global__ void k_scat1(const int* __restrict__ nb, const int* __restrict__ ne,
                        int* __restrict__ winner, int n_ent)
{
    int n = blockIdx.x * blockDim.x + threadIdx.x;
    if (n >= N_NODE) return;
    size_t slot = (size_t)nb[n] * n_ent + ne[n];
    atomicMax(&winner[slot], n);
}

__global__ void k_scat2(const float* __restrict__ h, const float* __restrict__ Wfinal,
                        const int* __restrict__ nb, const int* __restrict__ ne,
                        const int* __restrict__ winner, float* __restrict__ out, int n_ent)
{
    int n = (int)((blockIdx.x * blockDim.x + threadIdx.x) >> 5);
    int lane = threadIdx.x & 31;
    if (n >= N_NODE) return;
    float4 hv = ((const float4*)h)[(size_t)n * 32 + lane];
    float4 wv = ((const float4*)Wfinal)[lane];
    float s = hv.x * wv.x + hv.y * wv.y + hv.z * wv.z + hv.w * wv.w;
#pragma unroll
    for (int off = 16; off; off >>= 1) s += __shfl_xor_sync(0xffffffffu, s, off);
    if (lane == 0) {
        size_t slot = (size_t)nb[n] * n_ent + ne[n];
        if (winner[slot] == n) out[slot] = s;
    }
}

// ---------------- host launcher ----------------
extern "C" void kernel_launch(void* const* d_in, const int* in_sizes, int n_in,
                              void* d_out, int out_size)
{
    const float* rela     = (const float*)d_in[0];
    const float* Ws       = (const float*)d_in[1];
    const float* Wr       = (const float*)d_in[2];
    const float* Wqr_w    = (const float*)d_in[3];
    const float* Wqr_b    = (const float*)d_in[4];
    const float* Wtau     = (const float*)d_in[5];
    const float* walpha_w = (const float*)d_in[6];
    const float* walpha_b = (const float*)d_in[7];
    const float* Wh       = (const float*)d_in[8];
    const float* wt1      = (const float*)d_in[9];
    const float* bt1      = (const float*)d_in[10];
    const float* wt2      = (const float*)d_in[11];
    const float* bt2      = (const float*)d_in[12];
    const float* Wih      = (const float*)d_in[13];
    const float* Whh      = (const float*)d_in[14];
    const float* bih      = (const float*)d_in[15];
    const float* bhh      = (const float*)d_in[16];
    const float* Wfinal   = (const float*)d_in[17];
    const int*   q_rel    = (const int*)d_in[18];
    const int*   q_tau    = (const int*)d_in[19];
    const int*   e_ridx   = (const int*)d_in[20];
    const int*   e_rel    = (const int*)d_in[21];
    const int*   e_tau    = (const int*)d_in[22];
    const int*   e_sub    = (const int*)d_in[23];
    const int*   e_obj    = (const int*)d_in[24];
    const int*   nb       = (const int*)d_in[25];
    const int*   ne       = (const int*)d_in[26];

    int nq    = in_sizes[18];
    int n_ent = out_size / nq;

    float *hprev, *hidden1, *agg, *gi, *gh, *Hmsg;
    __half *HS16, *h16, *Rattn16, *Qattn16, *Hattn16;
    int* winner;
    cudaGetSymbolAddress((void**)&hprev,   g_hprev);
    cudaGetSymbolAddress((void**)&hidden1, g_hidden1);
    cudaGetSymbolAddress((void**)&agg,     g_agg);
    cudaGetSymbolAddress((void**)&gi,      g_gi);
    cudaGetSymbolAddress((void**)&gh,      g_gh);
    cudaGetSymbolAddress((void**)&HS16,    g_HS16);
    cudaGetSymbolAddress((void**)&h16,     g_h16);
    cudaGetSymbolAddress((void**)&Rattn16, g_Rattn16);
    cudaGetSymbolAddress((void**)&Qattn16, g_Qattn16);
    cudaGetSymbolAddress((void**)&Hattn16, g_Hattn16);
    cudaGetSymbolAddress((void**)&Hmsg,    g_Hmsg);
    cudaGetSymbolAddress((void**)&winner,  g_winner);

    cudaFuncSetAttribute(k_mma, cudaFuncAttributeMaxDynamicSharedMemorySize, SMEM_MMA);

    cudaMemsetAsync(hprev, 0, sizeof(float) * (size_t)N_NODE * D_DIM);

    const int mblocks = (N_NODE + 127) / 128;   // 782

    for (int l = 0; l < L_LAYERS; l++) {
        cudaMemsetAsync(agg, 0, sizeof(float) * (size_t)N_NODE * D_DIM);

        k_tab_rq<<<NREL + NQ_C, 64>>>(rela + (size_t)l * NREL * 128,
                                      Wr + (size_t)l * 64 * 128,
                                      Wqr_w + (size_t)l * 64 * 128,
                                      Wqr_b + (size_t)l * 64,
                                      q_rel, Rattn16, Qattn16);
        k_tab_delta<<<N_DELTA, 128>>>(wt1 + (size_t)l * 128, bt1 + (size_t)l * 128,
                                      wt2 + (size_t)l * 128, bt2 + (size_t)l * 128,
                                      Wtau + (size_t)l * 64 * 128, Hmsg, Hattn16);

        if (l > 0) {
            // shared-A: HS16 = fp16(hprev@Ws^T)  and  gh = hprev@Whh^T + bhh
            k_mma<<<mblocks, 256, SMEM_MMA>>>(hprev, N_NODE,
                                              Ws + (size_t)l * 64 * 128, nullptr,
                                              (float*)HS16, 64, 0,
                                              Whh + (size_t)l * 384 * 128,
                                              bhh + (size_t)l * 384, gh, 384, 0, 1);
        }

        k_edge<<<N_EDGE / 8, 256>>>(e_sub + (size_t)l * N_EDGE, e_rel + (size_t)l * N_EDGE,
                                    e_obj + (size_t)l * N_EDGE, e_ridx + (size_t)l * N_EDGE,
                                    e_tau + (size_t)l * N_EDGE, q_tau,
                                    HS16, Rattn16, Qattn16, Hattn16, Hmsg, h16,
                                    rela + (size_t)l * NREL * 128,
                                    walpha_w + (size_t)l * 64, walpha_b + l, agg,
                                    (l == 0) ? 1 : 0);

        // hidden1 = relu(agg @ Wh^T)
        k_mma<<<mblocks, 256, SMEM_MMA>>>(agg, N_NODE,
                                          Wh + (size_t)l * 128 * 128, nullptr, hidden1, 128, 1,
                                          nullptr, nullptr, nullptr, 0, 0, 0);
        // gi = hidden1 @ Wih^T + bih
        k_mma<<<mblocks, 256, SMEM_MMA>>>(hidden1, N_NODE,
                                          Wih + (size_t)l * 384 * 128,
                                          bih + (size_t)l * 384, gi, 384, 0,
                                          nullptr, nullptr, nullptr, 0, 0, 0);
        // hprev <- GRU (also writes fp16 shadow for next layer's edge gathers)
        k_gru<<<(N_NODE * 32) / 256, 256>>>(gi, (l > 0) ? gh : nullptr,
                                            bhh + (size_t)l * 384, hprev, h16);
    }

    cudaMemsetAsync(d_out, 0, (size_t)out_size * sizeof(float));
    k_scat0<<<(N_NODE + 255) / 256, 256>>>(nb, ne, winner, n_ent);
    k_scat1<<<(N_NODE + 255) / 256, 256>>>(nb, ne, winner, n_ent);
    k_scat2<<<(N_NODE * 32) / 256, 256>>>(hprev, Wfinal, nb, ne, winner, (float*)d_out, n_ent);
}

// round 15
// speedup vs baseline: 1.1612x; 1.0252x over previous
#include <cuda_runtime.h>
#include <cuda_bf16.h>
#include <cuda_fp16.h>
#include <math.h>

#define L_LAYERS 3
#define D_DIM    128
#define A_DIM    64
#define NREL     401
#define N_NODE   100000
#define N_EDGE   600000
#define NQ_C     512
#define N_DELTA  731
#define MAX_OUT  (512*50000)

// bf16x2-packed planes, stride 68 words (64 k-pairs + pad, mod32=4)
#define AST 68
#define SMEM_MMA ((128 + 128 + 64 + 64) * AST * 4)   // 104448 B -> 2 CTAs/SM

// ---------------- static device scratch ----------------
__device__ float  g_hprev  [N_NODE * D_DIM];
__device__ float  g_hidden1[N_NODE * D_DIM];
__device__ float  g_agg    [N_NODE * D_DIM];
__device__ __half g_gi16   [N_NODE * 3 * D_DIM];
__device__ __half g_gh16   [N_NODE * 3 * D_DIM];
__device__ __half g_HS16   [N_NODE * A_DIM];
__device__ __half g_h16    [N_NODE * D_DIM];
__device__ __half g_Rattn16[NREL * A_DIM];
__device__ __half g_Qattn16[NQ_C * A_DIM];
__device__ __half g_Hattn16[N_DELTA * A_DIM];
__device__ float  g_Hmsg   [N_DELTA * D_DIM];
__device__ int    g_winner [MAX_OUT];

__device__ __forceinline__ float sigmoidf_(float x) { return 1.0f / (1.0f + expf(-x)); }

__device__ __forceinline__ unsigned pack_bf2(float x0, float x1) {
    unsigned r;
    asm("cvt.rn.bf16x2.f32 %0, %1, %2;" : "=r"(r) : "f"(x1), "f"(x0));
    return r;
}
__device__ __forceinline__ void split_pair(float x0, float x1, unsigned& h, unsigned& l) {
    h = pack_bf2(x0, x1);
    float h0 = __uint_as_float(h << 16);
    float h1 = __uint_as_float(h & 0xFFFF0000u);
    l = pack_bf2(x0 - h0, x1 - h1);
}

__device__ __forceinline__ void mma_bf16(float* c,
                                         unsigned a0, unsigned a1, unsigned a2, unsigned a3,
                                         unsigned b0, unsigned b1) {
    asm volatile(
        "mma.sync.aligned.m16n8k16.row.col.f32.bf16.bf16.f32 "
        "{%0,%1,%2,%3}, {%4,%5,%6,%7}, {%8,%9}, {%0,%1,%2,%3};"
        : "+f"(c[0]), "+f"(c[1]), "+f"(c[2]), "+f"(c[3])
        : "r"(a0), "r"(a1), "r"(a2), "r"(a3), "r"(b0), "r"(b1));
}

__device__ __forceinline__ void ldsm_x4(unsigned& r0, unsigned& r1,
                                        unsigned& r2, unsigned& r3, unsigned addr) {
    asm volatile("ldmatrix.sync.aligned.m8n8.x4.shared.b16 {%0,%1,%2,%3}, [%4];"
                 : "=r"(r0), "=r"(r1), "=r"(r2), "=r"(r3) : "r"(addr));
}

// ---------------- per-relation / per-query attention tables (fp16 out) ----------------
__global__ void k_tab_rq(const float* __restrict__ rela_l,
                         const float* __restrict__ Wr_l,
                         const float* __restrict__ Wqr_w_l,
                         const float* __restrict__ Wqr_b_l,
                         const int*   __restrict__ q_rel,
                         __half* __restrict__ Rattn,
                         __half* __restrict__ Qattn)
{
    __shared__ float hv[128];
    int b = blockIdx.x;
    int a = threadIdx.x; // 0..63
    const float* src = (b < NREL) ? (rela_l + (size_t)b * 128)
                                  : (rela_l + (size_t)q_rel[b - NREL] * 128);
    hv[a] = src[a];
    hv[a + 64] = src[a + 64];
    __syncthreads();
    const float* W = ((b < NREL) ? Wr_l : Wqr_w_l) + (size_t)a * 128;
    float s = 0.f;
#pragma unroll
    for (int k = 0; k < 128; k += 4) {
        float4 w = *(const float4*)(W + k);
        s += hv[k] * w.x + hv[k + 1] * w.y + hv[k + 2] * w.z + hv[k + 3] * w.w;
    }
    if (b < NREL) Rattn[b * 64 + a] = __float2half(s);
    else          Qattn[(b - NREL) * 64 + a] = __float2half(s + Wqr_b_l[a]);
}

// ---------------- per-delta tables (Hmsg fp32, Hattn fp16) ----------------
__global__ void k_tab_delta(const float* __restrict__ wt1, const float* __restrict__ bt1,
                            const float* __restrict__ wt2, const float* __restrict__ bt2,
                            const float* __restrict__ Wtau_l,
                            float* __restrict__ Hmsg, __half* __restrict__ Hattn)
{
    __shared__ float hh[128];
    int di = blockIdx.x;           // 0..730
    float delta = (float)(di - 365);
    int d = threadIdx.x;           // 0..127
    float v = wt1[d] * delta + bt1[d] + sinf(wt2[d] * delta + bt2[d]);
    hh[d] = v;
    Hmsg[(size_t)di * 128 + d] = v;
    __syncthreads();
    if (d < 64) {
        const float* W = Wtau_l + (size_t)d * 128;
        float s = 0.f;
#pragma unroll
        for (int k = 0; k < 128; k += 4) {
            float4 w = *(const float4*)(W + k);
            s += hh[k] * w.x + hh[k + 1] * w.y + hh[k + 2] * w.z + hh[k + 3] * w.w;
        }
        Hattn[(size_t)di * 64 + d] = __float2half(s);
    }
}

// ---------------- edge kernel: one warp per edge ----------------
// Attention tables fp16 (half2 sums); message: rela/Hmsg fp32, hs fp16.
__global__ void __launch_bounds__(256) k_edge(
    const int* __restrict__ e_sub, const int* __restrict__ e_rel,
    const int* __restrict__ e_obj, const int* __restrict__ e_ridx,
    const int* __restrict__ e_tau, const int* __restrict__ q_tau,
    const __half* __restrict__ HS16, const __half* __restrict__ Rattn16,
    const __half* __restrict__ Qattn16, const __half* __restrict__ Hattn16,
    const float* __restrict__ Hmsg, const __half* __restrict__ h16,
    const float* __restrict__ rela_l, const float* __restrict__ walpha_w_l,
    const float* __restrict__ walpha_b_l, float* __restrict__ agg, int zero_h)
{
    int e = (int)((blockIdx.x * blockDim.x + threadIdx.x) >> 5);
    int lane = threadIdx.x & 31;
    if (e >= N_EDGE) return;

    int s_ = e_sub[e];
    int r_ = e_rel[e];
    int o_ = e_obj[e];
    int q_ = e_ridx[e];
    int t_ = e_tau[e];
    int tq = q_tau[q_];
    int tau = (t_ >= 0) ? t_ : tq;
    int di = tau - tq + 365;
    di = min(max(di, 0), 730);

    // attention: half2 sums of fp16 tables, one convert at the end
    __half2 ra = ((const __half2*)Rattn16)[(size_t)r_ * 32 + lane];
    __half2 qa = ((const __half2*)Qattn16)[(size_t)q_ * 32 + lane];
    __half2 ta = ((const __half2*)Hattn16)[(size_t)di * 32 + lane];
    __half2 s2 = __hadd2(__hadd2(ra, qa), ta);
    if (!zero_h) {
        __half2 hsa = ((const __half2*)HS16)[(size_t)s_ * 32 + lane];
        s2 = __hadd2(s2, hsa);
    }
    float2 a2 = __half22float2(s2);
    float vx = fmaxf(a2.x, 0.f);
    float vy = fmaxf(a2.y, 0.f);
    float2 wa = ((const float2*)walpha_w_l)[lane];
    float acc = vx * wa.x + vy * wa.y;
#pragma unroll
    for (int off = 16; off; off >>= 1) acc += __shfl_xor_sync(0xffffffffu, acc, off);
    float alpha = 1.0f / (1.0f + expf(-(acc + walpha_b_l[0])));

    // message: fp32 rela + fp32 Hmsg (+ fp16 hs gather)
    float4 r4 = ((const float4*)(rela_l + (size_t)r_ * 128))[lane];
    float4 m4 = ((const float4*)(Hmsg   + (size_t)di * 128))[lane];
    float mx = r4.x + m4.x, my = r4.y + m4.y;
    float mz = r4.z + m4.z, mw = r4.w + m4.w;
    if (!zero_h) {
        uint2 hv = ((const uint2*)(h16 + (size_t)s_ * 128))[lane];
        float2 h0 = __half22float2(*(const __half2*)&hv.x);
        float2 h1 = __half22float2(*(const __half2*)&hv.y);
        mx += h0.x; my += h0.y; mz += h1.x; mw += h1.y;
    }
    mx *= alpha; my *= alpha; mz *= alpha; mw *= alpha;
    float* dst = agg + (size_t)o_ * 128 + lane * 4;
    asm volatile("red.global.add.v4.f32 [%0], {%1,%2,%3,%4};"
                 :: "l"(dst), "f"(mx), "f"(my), "f"(mz), "f"(mw) : "memory");
}

// ---------------- GEMM: bf16 split planes + ldmatrix, two weight segments ----------------
// c1half/c2half: segment output written as fp16.
__global__ void __launch_bounds__(256, 2) k_mma(
    const float* __restrict__ A, int M,
    const float* __restrict__ W1, const float* __restrict__ bias1,
    float* __restrict__ C1, int N1, int relu1,
    const float* __restrict__ W2, const float* __restrict__ bias2,
    float* __restrict__ C2, int N2, int relu2, int c1half, int c2half)
{
    extern __shared__ unsigned sm[];
    unsigned* Ah = sm;                  // [128][AST]
    unsigned* Al = sm + 128 * AST;
    unsigned* Bh = sm + 256 * AST;      // [64][AST]
    unsigned* Bl = sm + 320 * AST;

    int tid  = threadIdx.x;
    int bm   = blockIdx.x * 128;
    int lane = tid & 31;
    int warp = tid >> 5;
    int wm   = (warp & 3) * 32;
    int wn   = (warp >> 2) * 32;
    int gr   = lane >> 2;
    int tg   = lane & 3;
    int quad = lane >> 3;
    int lrow = lane & 7;

    for (int i = tid; i < 128 * 32; i += 256) {
        int row = i >> 5;
        int c4  = (i & 31) * 4;
        int grow = bm + row;
        float4 v = (grow < M) ? *(const float4*)(A + (size_t)grow * 128 + c4)
                              : make_float4(0.f, 0.f, 0.f, 0.f);
        unsigned h0, l0, h1, l1;
        split_pair(v.x, v.y, h0, l0);
        split_pair(v.z, v.w, h1, l1);
        int p = row * AST + (c4 >> 1);
        Ah[p] = h0; Ah[p + 1] = h1;
        Al[p] = l0; Al[p + 1] = l1;
    }
    __syncthreads();

    unsigned AhU = (unsigned)__cvta_generic_to_shared(Ah);
    unsigned AlU = (unsigned)__cvta_generic_to_shared(Al);
    unsigned BhU = (unsigned)__cvta_generic_to_shared(Bh);
    unsigned BlU = (unsigned)__cvta_generic_to_shared(Bl);
    unsigned aOff = (unsigned)(((wm + (quad & 1) * 8 + lrow) * AST) * 4 + (quad >> 1) * 16);
    unsigned aAd[2][2];
    aAd[0][0] = AhU + aOff;                 aAd[0][1] = AlU + aOff;
    aAd[1][0] = AhU + aOff + 16 * AST * 4;  aAd[1][1] = AlU + aOff + 16 * AST * 4;
    unsigned bOff = (unsigned)(((wn + lane) * AST) * 4);
    unsigned bAdH = BhU + bOff;
    unsigned bAdL = BlU + bOff;

    int Ntot = N1 + N2;
    for (int nb = 0; nb < Ntot; nb += 64) {
        const float* Wseg; const float* bseg; float* Cseg; int nloc, Nseg, reluseg, halfseg;
        if (nb < N1) { Wseg = W1; bseg = bias1; Cseg = C1; nloc = nb;      Nseg = N1; reluseg = relu1; halfseg = c1half; }
        else         { Wseg = W2; bseg = bias2; Cseg = C2; nloc = nb - N1; Nseg = N2; reluseg = relu2; halfseg = c2half; }

        for (int i = tid; i < 64 * 32; i += 256) {
            int row = i >> 5;
            int c4  = (i & 31) * 4;
            float4 v = *(const float4*)(Wseg + (size_t)(nloc + row) * 128 + c4);
            unsigned h0, l0, h1, l1;
            split_pair(v.x, v.y, h0, l0);
            split_pair(v.z, v.w, h1, l1);
            int p = row * AST + (c4 >> 1);
            Bh[p] = h0; Bh[p + 1] = h1;
            Bl[p] = l0; Bl[p + 1] = l1;
        }
        __syncthreads();

        float acc[2][4][4];
#pragma unroll
        for (int mt = 0; mt < 2; mt++)
#pragma unroll
            for (int nt = 0; nt < 4; nt++)
#pragma unroll
                for (int r = 0; r < 4; r++) acc[mt][nt][r] = 0.f;

#pragma unroll
        for (int it = 0; it < 8; it++) {
            unsigned off = it * 32;
            unsigned ah[2][4], al[2][4];
#pragma unroll
            for (int mt = 0; mt < 2; mt++) {
                ldsm_x4(ah[mt][0], ah[mt][1], ah[mt][2], ah[mt][3], aAd[mt][0] + off);
                ldsm_x4(al[mt][0], al[mt][1], al[mt][2], al[mt][3], aAd[mt][1] + off);
            }
            unsigned bhlo[4], bhhi[4], bllo[4], blhi[4];
            ldsm_x4(bhlo[0], bhlo[1], bhlo[2], bhlo[3], bAdH + off);
            ldsm_x4(bhhi[0], bhhi[1], bhhi[2], bhhi[3], bAdH + off + 16);
            ldsm_x4(bllo[0], bllo[1], bllo[2], bllo[3], bAdL + off);
            ldsm_x4(blhi[0], blhi[1], blhi[2], blhi[3], bAdL + off + 16);
#pragma unroll
            for (int mt = 0; mt < 2; mt++)
#pragma unroll
                for (int nt = 0; nt < 4; nt++) {
                    mma_bf16(acc[mt][nt], ah[mt][0], ah[mt][1], ah[mt][2], ah[mt][3],
                             bhlo[nt], bhhi[nt]);
                    mma_bf16(acc[mt][nt], ah[mt][0], ah[mt][1], ah[mt][2], ah[mt][3],
                             bllo[nt], blhi[nt]);
                    mma_bf16(acc[mt][nt], al[mt][0], al[mt][1], al[mt][2], al[mt][3],
                             bhlo[nt], bhhi[nt]);
                }
        }
        __syncthreads();

#pragma unroll
        for (int mt = 0; mt < 2; mt++) {
#pragma unroll
            for (int nt = 0; nt < 4; nt++) {
                int col = nloc + wn + nt * 8 + 2 * tg;
                float bx = 0.f, by = 0.f;
                if (bseg) { bx = bseg[col]; by = bseg[col + 1]; }
                int row0 = bm + wm + mt * 16 + gr;
                int row1 = row0 + 8;
                float2 v0 = make_float2(acc[mt][nt][0] + bx, acc[mt][nt][1] + by);
                float2 v1 = make_float2(acc[mt][nt][2] + bx, acc[mt][nt][3] + by);
                if (reluseg) {
                    v0.x = fmaxf(v0.x, 0.f); v0.y = fmaxf(v0.y, 0.f);
                    v1.x = fmaxf(v1.x, 0.f); v1.y = fmaxf(v1.y, 0.f);
                }
                if (halfseg) {
                    __half* Ch = (__half*)Cseg;
                    if (row0 < M) *(__half2*)(Ch + (size_t)row0 * Nseg + col) = __floats2half2_rn(v0.x, v0.y);
                    if (row1 < M) *(__half2*)(Ch + (size_t)row1 * Nseg + col) = __floats2half2_rn(v1.x, v1.y);
                } else {
                    if (row0 < M) *(float2*)(Cseg + (size_t)row0 * Nseg + col) = v0;
                    if (row1 < M) *(float2*)(Cseg + (size_t)row1 * Nseg + col) = v1;
                }
            }
        }
    }
}

// ---------------- GRU elementwise: fp16 gi/gh inputs; emits fp16 shadow of h ----------------
__global__ void k_gru(const __half* __restrict__ gi, const __half* __restrict__ gh,
                      const float* __restrict__ bhh, float* __restrict__ h,
                      __half* __restrict__ h16)
{
    int idx = blockIdx.x * blockDim.x + threadIdx.x;
    if (idx >= N_NODE * 32) return;
    int n = idx >> 5, g = idx & 31;
    const __half2* gi2 = (const __half2*)(gi + (size_t)n * 384);
    float2 ir01 = __half22float2(gi2[g * 2]);
    float2 ir23 = __half22float2(gi2[g * 2 + 1]);
    float2 iz01 = __half22float2(gi2[64 + g * 2]);
    float2 iz23 = __half22float2(gi2[64 + g * 2 + 1]);
    float2 in01 = __half22float2(gi2[128 + g * 2]);
    float2 in23 = __half22float2(gi2[128 + g * 2 + 1]);
    float4 ir = make_float4(ir01.x, ir01.y, ir23.x, ir23.y);
    float4 iz = make_float4(iz01.x, iz01.y, iz23.x, iz23.y);
    float4 in_ = make_float4(in01.x, in01.y, in23.x, in23.y);
    float4 hr, hz, hn;
    if (gh) {
        const __half2* gh2 = (const __half2*)(gh + (size_t)n * 384);
        float2 a0 = __half22float2(gh2[g * 2]);
        float2 a1 = __half22float2(gh2[g * 2 + 1]);
        float2 b0 = __half22float2(gh2[64 + g * 2]);
        float2 b1 = __half22float2(gh2[64 + g * 2 + 1]);
        float2 c0 = __half22float2(gh2[128 + g * 2]);
        float2 c1 = __half22float2(gh2[128 + g * 2 + 1]);
        hr = make_float4(a0.x, a0.y, a1.x, a1.y);
        hz = make_float4(b0.x, b0.y, b1.x, b1.y);
        hn = make_float4(c0.x, c0.y, c1.x, c1.y);
    } else {
        const float4* b4 = (const float4*)bhh;
        hr = b4[g]; hz = b4[32 + g]; hn = b4[64 + g];
    }
    float4 h0 = ((const float4*)h)[(size_t)n * 32 + g];
    float4 out;
    {
        float r = sigmoidf_(ir.x + hr.x), z = sigmoidf_(iz.x + hz.x);
        float nn = tanhf(in_.x + r * hn.x);
        out.x = (1.f - z) * nn + z * h0.x;
    }
    {
        float r = sigmoidf_(ir.y + hr.y), z = sigmoidf_(iz.y + hz.y);
        float nn = tanhf(in_.y + r * hn.y);
        out.y = (1.f - z) * nn + z * h0.y;
    }
    {
        float r = sigmoidf_(ir.z + hr.z), z = sigmoidf_(iz.z + hz.z);
        float nn = tanhf(in_.z + r * hn.z);
        out.z = (1.f - z) * nn + z * h0.z;
    }
    {
        float r = sigmoidf_(ir.w + hr.w), z = sigmoidf_(iz.w + hz.w);
        float nn = tanhf(in_.w + r * hn.w);
        out.w = (1.f - z) * nn + z * h0.w;
    }
    ((float4*)h)[(size_t)n * 32 + g] = out;
    __half2* hp = (__half2*)(h16 + (size_t)n * 128 + g * 4);
    hp[0] = __floats2half2_rn(out.x, out.y);
    hp[1] = __floats2half2_rn(out.z, out.w);
}

// ---------------- output scatter ----------------
__global__ void k_scat0(const int* __restrict__ nb, const int* __restrict__ ne,
                        int* __restrict__ winner, int n_ent)
{
    int n = blockIdx.x * blockDim.x + threadIdx.x;
    if (n >= N_NODE) return;
    winner[(size_t)nb[n] * n_ent + ne[n]] = -1;
}

__global__ void k_scat1(const int* __restrict__ nb, const int* __restrict__ ne,
                        int* __restrict__ winner, int n_ent)
{
    int n = blockIdx.x * blockDim.x + threadIdx.x;
    if (n >= N_NODE) return;
    size_t slot = (size_t)nb[n] * n_ent + ne[n];
    atomicMax(&winner[slot], n);
}

__global__ void k_scat2(const float* __restrict__ h, const float* __restrict__ Wfinal,
                        const int* __restrict__ nb, const int* __restrict__ ne,
                        const int* __restrict__ winner, float* __restrict__ out, int n_ent)
{
    int n = (int)((blockIdx.x * blockDim.x + threadIdx.x) >> 5);
    int lane = threadIdx.x & 31;
    if (n >= N_NODE) return;
    float4 hv = ((const float4*)h)[(size_t)n * 32 + lane];
    float4 wv = ((const float4*)Wfinal)[lane];
    float s = hv.x * wv.x + hv.y * wv.y + hv.z * wv.z + hv.w * wv.w;
#pragma unroll
    for (int off = 16; off; off >>= 1) s += __shfl_xor_sync(0xffffffffu, s, off);
    if (lane == 0) {
        size_t slot = (size_t)nb[n] * n_ent + ne[n];
        if (winner[slot] == n) out[slot] = s;
    }
}

// ---------------- host launcher ----------------
extern "C" void kernel_launch(void* const* d_in, const int* in_sizes, int n_in,
                              void* d_out, int out_size)
{
    const float* rela     = (const float*)d_in[0];
    const float* Ws       = (const float*)d_in[1];
    const float* Wr       = (const float*)d_in[2];
    const float* Wqr_w    = (const float*)d_in[3];
    const float* Wqr_b    = (const float*)d_in[4];
    const float* Wtau     = (const float*)d_in[5];
    const float* walpha_w = (const float*)d_in[6];
    const float* walpha_b = (const float*)d_in[7];
    const float* Wh       = (const float*)d_in[8];
    const float* wt1      = (const float*)d_in[9];
    const float* bt1      = (const float*)d_in[10];
    const float* wt2      = (const float*)d_in[11];
    const float* bt2      = (const float*)d_in[12];
    const float* Wih      = (const float*)d_in[13];
    const float* Whh      = (const float*)d_in[14];
    const float* bih      = (const float*)d_in[15];
    const float* bhh      = (const float*)d_in[16];
    const float* Wfinal   = (const float*)d_in[17];
    const int*   q_rel    = (const int*)d_in[18];
    const int*   q_tau    = (const int*)d_in[19];
    const int*   e_ridx   = (const int*)d_in[20];
    const int*   e_rel    = (const int*)d_in[21];
    const int*   e_tau    = (const int*)d_in[22];
    const int*   e_sub    = (const int*)d_in[23];
    const int*   e_obj    = (const int*)d_in[24];
    const int*   nb       = (const int*)d_in[25];
    const int*   ne       = (const int*)d_in[26];

    int nq    = in_sizes[18];
    int n_ent = out_size / nq;

    float *hprev, *hidden1, *agg, *Hmsg;
    __half *gi16, *gh16, *HS16, *h16, *Rattn16, *Qattn16, *Hattn16;
    int* winner;
    cudaGetSymbolAddress((void**)&hprev,   g_hprev);
    cudaGetSymbolAddress((void**)&hidden1, g_hidden1);
    cudaGetSymbolAddress((void**)&agg,     g_agg);
    cudaGetSymbolAddress((void**)&gi16,    g_gi16);
    cudaGetSymbolAddress((void**)&gh16,    g_gh16);
    cudaGetSymbolAddress((void**)&HS16,    g_HS16);
    cudaGetSymbolAddress((void**)&h16,     g_h16);
    cudaGetSymbolAddress((void**)&Rattn16, g_Rattn16);
    cudaGetSymbolAddress((void**)&Qattn16, g_Qattn16);
    cudaGetSymbolAddress((void**)&Hattn16, g_Hattn16);
    cudaGetSymbolAddress((void**)&Hmsg,    g_Hmsg);
    cudaGetSymbolAddress((void**)&winner,  g_winner);

    cudaFuncSetAttribute(k_mma, cudaFuncAttributeMaxDynamicSharedMemorySize, SMEM_MMA);

    cudaMemsetAsync(hprev, 0, sizeof(float) * (size_t)N_NODE * D_DIM);

    const int mblocks = (N_NODE + 127) / 128;   // 782

    for (int l = 0; l < L_LAYERS; l++) {
        cudaMemsetAsync(agg, 0, sizeof(float) * (size_t)N_NODE * D_DIM);

        k_tab_rq<<<NREL + NQ_C, 64>>>(rela + (size_t)l * NREL * 128,
                                      Wr + (size_t)l * 64 * 128,
                                      Wqr_w + (size_t)l * 64 * 128,
                                      Wqr_b + (size_t)l * 64,
                                      q_rel, Rattn16, Qattn16);
        k_tab_delta<<<N_DELTA, 128>>>(wt1 + (size_t)l * 128, bt1 + (size_t)l * 128,
                                      wt2 + (size_t)l * 128, bt2 + (size_t)l * 128,
                                      Wtau + (size_t)l * 64 * 128, Hmsg, Hattn16);

        if (l > 0) {
            // shared-A: HS16 = fp16(hprev@Ws^T)  and  gh16 = fp16(hprev@Whh^T + bhh)
            k_mma<<<mblocks, 256, SMEM_MMA>>>(hprev, N_NODE,
                                              Ws + (size_t)l * 64 * 128, nullptr,
                                              (float*)HS16, 64, 0,
                                              Whh + (size_t)l * 384 * 128,
                                              bhh + (size_t)l * 384, (float*)gh16, 384, 0,
                                              1, 1);
        }

        k_edge<<<N_EDGE / 8, 256>>>(e_sub + (size_t)l * N_EDGE, e_rel + (size_t)l * N_EDGE,
                                    e_obj + (size_t)l * N_EDGE, e_ridx + (size_t)l * N_EDGE,
                                    e_tau + (size_t)l * N_EDGE, q_tau,
                                    HS16, Rattn16, Qattn16, Hattn16, Hmsg, h16,
                                    rela + (size_t)l * NREL * 128,
                                    walpha_w + (size_t)l * 64, walpha_b + l, agg,
                                    (l == 0) ? 1 : 0);

        // hidden1 = relu(agg @ Wh^T)  (fp32)
        k_mma<<<mblocks, 256, SMEM_MMA>>>(agg, N_NODE,
                                          Wh + (size_t)l * 128 * 128, nullptr, hidden1, 128, 1,
                                          nullptr, nullptr, nullptr, 0, 0, 0, 0);
        // gi16 = fp16(hidden1 @ Wih^T + bih)
        k_mma<<<mblocks, 256, SMEM_MMA>>>(hidden1, N_NODE,
                                          Wih + (size_t)l * 384 * 128,
                                          bih + (size_t)l * 384, (float*)gi16, 384, 0,
                                          nullptr, nullptr, nullptr, 0, 0, 1, 0);
        // hprev <- GRU (reads fp16 gi/gh; writes fp16 shadow for next layer's edge gathers)
        k_gru<<<(N_NODE * 32) / 256, 256>>>(gi16, (l > 0) ? gh16 : nullptr,
                                            bhh + (size_t)l * 384, hprev, h16);
    }

    cudaMemsetAsync(d_out, 0, (size_t)out_size * sizeof(float));
    k_scat0<<<(N_NODE + 255) / 256, 256>>>(nb, ne, winner, n_ent);
    k_scat1<<<(N_NODE + 255) / 256, 256>>>(nb, ne, winner, n_ent);
    k_scat2<<<(N_NODE * 32) / 256, 256>>>(hprev, Wfinal, nb, ne, winner, (float*)d_out, n_ent);
}

// round 16
// speedup vs baseline: 1.1990x; 1.0325x over previous
#include <cuda_runtime.h>
#include <cuda_bf16.h>
#include <cuda_fp16.h>
#include <math.h>

#define L_LAYERS 3
#define D_DIM    128
#define A_DIM    64
#define NREL     401
#define N_NODE   100000
#define N_EDGE   600000
#define NQ_C     512
#define N_DELTA  731
#define MAX_OUT  (512*50000)

// bf16x2-packed planes, stride 68 words (64 k-pairs + pad, mod32=4)
#define AST 68
#define SMEM_MMA ((128 + 128 + 64 + 64) * AST * 4)   // 104448 B -> 2 CTAs/SM

// ---------------- static device scratch ----------------
__device__ float  g_hprev  [N_NODE * D_DIM];
__device__ __half g_hid16  [N_NODE * D_DIM];
__device__ float  g_agg    [N_NODE * D_DIM];
__device__ __half g_gi16   [N_NODE * 3 * D_DIM];
__device__ __half g_gh16   [N_NODE * 3 * D_DIM];
__device__ __half g_HS16   [N_NODE * A_DIM];
__device__ __half g_h16    [N_NODE * D_DIM];
__device__ __half g_Rattn16[NREL * A_DIM];
__device__ __half g_Qattn16[NQ_C * A_DIM];
__device__ __half g_Hattn16[N_DELTA * A_DIM];
__device__ float  g_Hmsg   [N_DELTA * D_DIM];
__device__ int    g_winner [MAX_OUT];

__device__ __forceinline__ float sigmoidf_(float x) { return 1.0f / (1.0f + expf(-x)); }

__device__ __forceinline__ unsigned pack_bf2(float x0, float x1) {
    unsigned r;
    asm("cvt.rn.bf16x2.f32 %0, %1, %2;" : "=r"(r) : "f"(x1), "f"(x0));
    return r;
}
__device__ __forceinline__ void split_pair(float x0, float x1, unsigned& h, unsigned& l) {
    h = pack_bf2(x0, x1);
    float h0 = __uint_as_float(h << 16);
    float h1 = __uint_as_float(h & 0xFFFF0000u);
    l = pack_bf2(x0 - h0, x1 - h1);
}

__device__ __forceinline__ void mma_bf16(float* c,
                                         unsigned a0, unsigned a1, unsigned a2, unsigned a3,
                                         unsigned b0, unsigned b1) {
    asm volatile(
        "mma.sync.aligned.m16n8k16.row.col.f32.bf16.bf16.f32 "
        "{%0,%1,%2,%3}, {%4,%5,%6,%7}, {%8,%9}, {%0,%1,%2,%3};"
        : "+f"(c[0]), "+f"(c[1]), "+f"(c[2]), "+f"(c[3])
        : "r"(a0), "r"(a1), "r"(a2), "r"(a3), "r"(b0), "r"(b1));
}

__device__ __forceinline__ void ldsm_x4(unsigned& r0, unsigned& r1,
                                        unsigned& r2, unsigned& r3, unsigned addr) {
    asm volatile("ldmatrix.sync.aligned.m8n8.x4.shared.b16 {%0,%1,%2,%3}, [%4];"
                 : "=r"(r0), "=r"(r1), "=r"(r2), "=r"(r3) : "r"(addr));
}

// ---------------- per-relation / per-query attention tables (fp16 out) ----------------
__global__ void k_tab_rq(const float* __restrict__ rela_l,
                         const float* __restrict__ Wr_l,
                         const float* __restrict__ Wqr_w_l,
                         const float* __restrict__ Wqr_b_l,
                         const int*   __restrict__ q_rel,
                         __half* __restrict__ Rattn,
                         __half* __restrict__ Qattn)
{
    __shared__ float hv[128];
    int b = blockIdx.x;
    int a = threadIdx.x; // 0..63
    const float* src = (b < NREL) ? (rela_l + (size_t)b * 128)
                                  : (rela_l + (size_t)q_rel[b - NREL] * 128);
    hv[a] = src[a];
    hv[a + 64] = src[a + 64];
    __syncthreads();
    const float* W = ((b < NREL) ? Wr_l : Wqr_w_l) + (size_t)a * 128;
    float s = 0.f;
#pragma unroll
    for (int k = 0; k < 128; k += 4) {
        float4 w = *(const float4*)(W + k);
        s += hv[k] * w.x + hv[k + 1] * w.y + hv[k + 2] * w.z + hv[k + 3] * w.w;
    }
    if (b < NREL) Rattn[b * 64 + a] = __float2half(s);
    else          Qattn[(b - NREL) * 64 + a] = __float2half(s + Wqr_b_l[a]);
}

// ---------------- per-delta tables (Hmsg fp32, Hattn fp16) ----------------
__global__ void k_tab_delta(const float* __restrict__ wt1, const float* __restrict__ bt1,
                            const float* __restrict__ wt2, const float* __restrict__ bt2,
                            const float* __restrict__ Wtau_l,
                            float* __restrict__ Hmsg, __half* __restrict__ Hattn)
{
    __shared__ float hh[128];
    int di = blockIdx.x;           // 0..730
    float delta = (float)(di - 365);
    int d = threadIdx.x;           // 0..127
    float v = wt1[d] * delta + bt1[d] + sinf(wt2[d] * delta + bt2[d]);
    hh[d] = v;
    Hmsg[(size_t)di * 128 + d] = v;
    __syncthreads();
    if (d < 64) {
        const float* W = Wtau_l + (size_t)d * 128;
        float s = 0.f;
#pragma unroll
        for (int k = 0; k < 128; k += 4) {
            float4 w = *(const float4*)(W + k);
            s += hh[k] * w.x + hh[k + 1] * w.y + hh[k + 2] * w.z + hh[k + 3] * w.w;
        }
        Hattn[(size_t)di * 64 + d] = __float2half(s);
    }
}

// ---------------- edge kernel: one warp per edge ----------------
__global__ void __launch_bounds__(256) k_edge(
    const int* __restrict__ e_sub, const int* __restrict__ e_rel,
    const int* __restrict__ e_obj, const int* __restrict__ e_ridx,
    const int* __restrict__ e_tau, const int* __restrict__ q_tau,
    const __half* __restrict__ HS16, const __half* __restrict__ Rattn16,
    const __half* __restrict__ Qattn16, const __half* __restrict__ Hattn16,
    const float* __restrict__ Hmsg, const __half* __restrict__ h16,
    const float* __restrict__ rela_l, const float* __restrict__ walpha_w_l,
    const float* __restrict__ walpha_b_l, float* __restrict__ agg, int zero_h)
{
    int e = (int)((blockIdx.x * blockDim.x + threadIdx.x) >> 5);
    int lane = threadIdx.x & 31;
    if (e >= N_EDGE) return;

    int s_ = e_sub[e];
    int r_ = e_rel[e];
    int o_ = e_obj[e];
    int q_ = e_ridx[e];
    int t_ = e_tau[e];
    int tq = q_tau[q_];
    int tau = (t_ >= 0) ? t_ : tq;
    int di = tau - tq + 365;
    di = min(max(di, 0), 730);

    __half2 ra = ((const __half2*)Rattn16)[(size_t)r_ * 32 + lane];
    __half2 qa = ((const __half2*)Qattn16)[(size_t)q_ * 32 + lane];
    __half2 ta = ((const __half2*)Hattn16)[(size_t)di * 32 + lane];
    __half2 s2 = __hadd2(__hadd2(ra, qa), ta);
    if (!zero_h) {
        __half2 hsa = ((const __half2*)HS16)[(size_t)s_ * 32 + lane];
        s2 = __hadd2(s2, hsa);
    }
    float2 a2 = __half22float2(s2);
    float vx = fmaxf(a2.x, 0.f);
    float vy = fmaxf(a2.y, 0.f);
    float2 wa = ((const float2*)walpha_w_l)[lane];
    float acc = vx * wa.x + vy * wa.y;
#pragma unroll
    for (int off = 16; off; off >>= 1) acc += __shfl_xor_sync(0xffffffffu, acc, off);
    float alpha = 1.0f / (1.0f + expf(-(acc + walpha_b_l[0])));

    float4 r4 = ((const float4*)(rela_l + (size_t)r_ * 128))[lane];
    float4 m4 = ((const float4*)(Hmsg   + (size_t)di * 128))[lane];
    float mx = r4.x + m4.x, my = r4.y + m4.y;
    float mz = r4.z + m4.z, mw = r4.w + m4.w;
    if (!zero_h) {
        uint2 hv = ((const uint2*)(h16 + (size_t)s_ * 128))[lane];
        float2 h0 = __half22float2(*(const __half2*)&hv.x);
        float2 h1 = __half22float2(*(const __half2*)&hv.y);
        mx += h0.x; my += h0.y; mz += h1.x; mw += h1.y;
    }
    mx *= alpha; my *= alpha; mz *= alpha; mw *= alpha;
    float* dst = agg + (size_t)o_ * 128 + lane * 4;
    asm volatile("red.global.add.v4.f32 [%0], {%1,%2,%3,%4};"
                 :: "l"(dst), "f"(mx), "f"(my), "f"(mz), "f"(mw) : "memory");
}

// ---------------- GEMM: bf16 split planes + ldmatrix + B register prefetch ----------------
// ahalf: A is fp16. c1half/c2half: segment output written as fp16.
__global__ void __launch_bounds__(256, 2) k_mma(
    const float* __restrict__ A, int M, int ahalf,
    const float* __restrict__ W1, const float* __restrict__ bias1,
    float* __restrict__ C1, int N1, int relu1,
    const float* __restrict__ W2, const float* __restrict__ bias2,
    float* __restrict__ C2, int N2, int relu2, int c1half, int c2half)
{
    extern __shared__ unsigned sm[];
    unsigned* Ah = sm;                  // [128][AST]
    unsigned* Al = sm + 128 * AST;
    unsigned* Bh = sm + 256 * AST;      // [64][AST]
    unsigned* Bl = sm + 320 * AST;

    int tid  = threadIdx.x;
    int bm   = blockIdx.x * 128;
    int lane = tid & 31;
    int warp = tid >> 5;
    int wm   = (warp & 3) * 32;
    int wn   = (warp >> 2) * 32;
    int gr   = lane >> 2;
    int tg   = lane & 3;
    int quad = lane >> 3;
    int lrow = lane & 7;

    int prow = tid >> 1;                // B prefetch: 2 threads/row over 64 rows... (tid>>1 in 0..127)
    // B tile load mapping (as before): i = tid + k*256, row=i>>5, c4=(i&31)*4
    float4 bpre[8];
    {
        const float* W0 = (0 < N1) ? W1 : W2;   // tile 0 segment
#pragma unroll
        for (int k = 0; k < 8; k++) {
            int i = tid + k * 256;
            int row = i >> 5;
            int c4  = (i & 31) * 4;
            bpre[k] = *(const float4*)(W0 + (size_t)row * 128 + c4);
        }
    }
    (void)prow;

    // ---- load + split A tile ----
    for (int i = tid; i < 128 * 32; i += 256) {
        int row = i >> 5;
        int c4  = (i & 31) * 4;
        int grow = bm + row;
        float4 v;
        if (grow < M) {
            if (ahalf) {
                const __half* A16 = (const __half*)A;
                uint2 raw = *(const uint2*)(A16 + (size_t)grow * 128 + c4);
                float2 f0 = __half22float2(*(const __half2*)&raw.x);
                float2 f1 = __half22float2(*(const __half2*)&raw.y);
                v = make_float4(f0.x, f0.y, f1.x, f1.y);
            } else {
                v = *(const float4*)(A + (size_t)grow * 128 + c4);
            }
        } else {
            v = make_float4(0.f, 0.f, 0.f, 0.f);
        }
        unsigned h0, l0, h1, l1;
        split_pair(v.x, v.y, h0, l0);
        split_pair(v.z, v.w, h1, l1);
        int p = row * AST + (c4 >> 1);
        Ah[p] = h0; Ah[p + 1] = h1;
        Al[p] = l0; Al[p + 1] = l1;
    }
    __syncthreads();

    unsigned AhU = (unsigned)__cvta_generic_to_shared(Ah);
    unsigned AlU = (unsigned)__cvta_generic_to_shared(Al);
    unsigned BhU = (unsigned)__cvta_generic_to_shared(Bh);
    unsigned BlU = (unsigned)__cvta_generic_to_shared(Bl);
    unsigned aOff = (unsigned)(((wm + (quad & 1) * 8 + lrow) * AST) * 4 + (quad >> 1) * 16);
    unsigned aAd[2][2];
    aAd[0][0] = AhU + aOff;                 aAd[0][1] = AlU + aOff;
    aAd[1][0] = AhU + aOff + 16 * AST * 4;  aAd[1][1] = AlU + aOff + 16 * AST * 4;
    unsigned bOff = (unsigned)(((wn + lane) * AST) * 4);
    unsigned bAdH = BhU + bOff;
    unsigned bAdL = BlU + bOff;

    int Ntot = N1 + N2;
    for (int nb = 0; nb < Ntot; nb += 64) {
        const float* bseg; float* Cseg; int nloc, Nseg, reluseg, halfseg;
        if (nb < N1) { bseg = bias1; Cseg = C1; nloc = nb;      Nseg = N1; reluseg = relu1; halfseg = c1half; }
        else         { bseg = bias2; Cseg = C2; nloc = nb - N1; Nseg = N2; reluseg = relu2; halfseg = c2half; }

        // store prefetched B tile into smem planes (prior MMA done reading B:
        // guarded by the sync at the end of the previous iteration / A-load sync)
#pragma unroll
        for (int k = 0; k < 8; k++) {
            int i = tid + k * 256;
            int row = i >> 5;
            int c4  = (i & 31) * 4;
            unsigned h0, l0, h1, l1;
            split_pair(bpre[k].x, bpre[k].y, h0, l0);
            split_pair(bpre[k].z, bpre[k].w, h1, l1);
            int p = row * AST + (c4 >> 1);
            Bh[p] = h0; Bh[p + 1] = h1;
            Bl[p] = l0; Bl[p + 1] = l1;
        }
        __syncthreads();

        // prefetch next tile's B (latency hidden by MMA below)
        int nb2 = nb + 64;
        if (nb2 < Ntot) {
            const float* Wn; int nln;
            if (nb2 < N1) { Wn = W1; nln = nb2; } else { Wn = W2; nln = nb2 - N1; }
#pragma unroll
            for (int k = 0; k < 8; k++) {
                int i = tid + k * 256;
                int row = i >> 5;
                int c4  = (i & 31) * 4;
                bpre[k] = *(const float4*)(Wn + (size_t)(nln + row) * 128 + c4);
            }
        }

        float acc[2][4][4];
#pragma unroll
        for (int mt = 0; mt < 2; mt++)
#pragma unroll
            for (int nt = 0; nt < 4; nt++)
#pragma unroll
                for (int r = 0; r < 4; r++) acc[mt][nt][r] = 0.f;

#pragma unroll
        for (int it = 0; it < 8; it++) {
            unsigned off = it * 32;
            unsigned ah[2][4], al[2][4];
#pragma unroll
            for (int mt = 0; mt < 2; mt++) {
                ldsm_x4(ah[mt][0], ah[mt][1], ah[mt][2], ah[mt][3], aAd[mt][0] + off);
                ldsm_x4(al[mt][0], al[mt][1], al[mt][2], al[mt][3], aAd[mt][1] + off);
            }
            unsigned bhlo[4], bhhi[4], bllo[4], blhi[4];
            ldsm_x4(bhlo[0], bhlo[1], bhlo[2], bhlo[3], bAdH + off);
            ldsm_x4(bhhi[0], bhhi[1], bhhi[2], bhhi[3], bAdH + off + 16);
            ldsm_x4(bllo[0], bllo[1], bllo[2], bllo[3], bAdL + off);
            ldsm_x4(blhi[0], blhi[1], blhi[2], blhi[3], bAdL + off + 16);
#pragma unroll
            for (int mt = 0; mt < 2; mt++)
#pragma unroll
                for (int nt = 0; nt < 4; nt++) {
                    mma_bf16(acc[mt][nt], ah[mt][0], ah[mt][1], ah[mt][2], ah[mt][3],
                             bhlo[nt], bhhi[nt]);
                    mma_bf16(acc[mt][nt], ah[mt][0], ah[mt][1], ah[mt][2], ah[mt][3],
                             bllo[nt], blhi[nt]);
                    mma_bf16(acc[mt][nt], al[mt][0], al[mt][1], al[mt][2], al[mt][3],
                             bhlo[nt], bhhi[nt]);
                }
        }

        // epilogue
#pragma unroll
        for (int mt = 0; mt < 2; mt++) {
#pragma unroll
            for (int nt = 0; nt < 4; nt++) {
                int col = nloc + wn + nt * 8 + 2 * tg;
                float bx = 0.f, by = 0.f;
                if (bseg) { bx = bseg[col]; by = bseg[col + 1]; }
                int row0 = bm + wm + mt * 16 + gr;
                int row1 = row0 + 8;
                float2 v0 = make_float2(acc[mt][nt][0] + bx, acc[mt][nt][1] + by);
                float2 v1 = make_float2(acc[mt][nt][2] + bx, acc[mt][nt][3] + by);
                if (reluseg) {
                    v0.x = fmaxf(v0.x, 0.f); v0.y = fmaxf(v0.y, 0.f);
                    v1.x = fmaxf(v1.x, 0.f); v1.y = fmaxf(v1.y, 0.f);
                }
                if (halfseg) {
                    __half* Ch = (__half*)Cseg;
                    if (row0 < M) *(__half2*)(Ch + (size_t)row0 * Nseg + col) = __floats2half2_rn(v0.x, v0.y);
                    if (row1 < M) *(__half2*)(Ch + (size_t)row1 * Nseg + col) = __floats2half2_rn(v1.x, v1.y);
                } else {
                    if (row0 < M) *(float2*)(Cseg + (size_t)row0 * Nseg + col) = v0;
                    if (row1 < M) *(float2*)(Cseg + (size_t)row1 * Nseg + col) = v1;
                }
            }
        }
        __syncthreads();   // B smem reads done before next iteration's store
    }
}

// ---------------- GRU elementwise: fp16 gi/gh inputs; emits fp16 shadow of h ----------------
__global__ void k_gru(const __half* __restrict__ gi, const __half* __restrict__ gh,
                      const float* __restrict__ bhh, float* __restrict__ h,
                      __half* __restrict__ h16)
{
    int idx = blockIdx.x * blockDim.x + threadIdx.x;
    if (idx >= N_NODE * 32) return;
    int n = idx >> 5, g = idx & 31;
    const __half2* gi2 = (const __half2*)(gi + (size_t)n * 384);
    float2 ir01 = __half22float2(gi2[g * 2]);
    float2 ir23 = __half22float2(gi2[g * 2 + 1]);
    float2 iz01 = __half22float2(gi2[64 + g * 2]);
    float2 iz23 = __half22float2(gi2[64 + g * 2 + 1]);
    float2 in01 = __half22float2(gi2[128 + g * 2]);
    float2 in23 = __half22float2(gi2[128 + g * 2 + 1]);
    float4 ir = make_float4(ir01.x, ir01.y, ir23.x, ir23.y);
    float4 iz = make_float4(iz01.x, iz01.y, iz23.x, iz23.y);
    float4 in_ = make_float4(in01.x, in01.y, in23.x, in23.y);
    float4 hr, hz, hn;
    if (gh) {
        const __half2* gh2 = (const __half2*)(gh + (size_t)n * 384);
        float2 a0 = __half22float2(gh2[g * 2]);
        float2 a1 = __half22float2(gh2[g * 2 + 1]);
        float2 b0 = __half22float2(gh2[64 + g * 2]);
        float2 b1 = __half22float2(gh2[64 + g * 2 + 1]);
        float2 c0 = __half22float2(gh2[128 + g * 2]);
        float2 c1 = __half22float2(gh2[128 + g * 2 + 1]);
        hr = make_float4(a0.x, a0.y, a1.x, a1.y);
        hz = make_float4(b0.x, b0.y, b1.x, b1.y);
        hn = make_float4(c0.x, c0.y, c1.x, c1.y);
    } else {
        const float4* b4 = (const float4*)bhh;
        hr = b4[g]; hz = b4[32 + g]; hn = b4[64 + g];
    }
    float4 h0 = ((const float4*)h)[(size_t)n * 32 + g];
    float4 out;
    {
        float r = sigmoidf_(ir.x + hr.x), z = sigmoidf_(iz.x + hz.x);
        float nn = tanhf(in_.x + r * hn.x);
        out.x = (1.f - z) * nn + z * h0.x;
    }
    {
        float r = sigmoidf_(ir.y + hr.y), z = sigmoidf_(iz.y + hz.y);
        float nn = tanhf(in_.y + r * hn.y);
        out.y = (1.f - z) * nn + z * h0.y;
    }
    {
        float r = sigmoidf_(ir.z + hr.z), z = sigmoidf_(iz.z + hz.z);
        float nn = tanhf(in_.z + r * hn.z);
        out.z = (1.f - z) * nn + z * h0.z;
    }
    {
        float r = sigmoidf_(ir.w + hr.w), z = sigmoidf_(iz.w + hz.w);
        float nn = tanhf(in_.w + r * hn.w);
        out.w = (1.f - z) * nn + z * h0.w;
    }
    ((float4*)h)[(size_t)n * 32 + g] = out;
    __half2* hp = (__half2*)(h16 + (size_t)n * 128 + g * 4);
    hp[0] = __floats2half2_rn(out.x, out.y);
    hp[1] = __floats2half2_rn(out.z, out.w);
}

// ---------------- output scatter ----------------
__global__ void k_scat0(const int* __restrict__ nb, const int* __restrict__ ne,
                        int* __restrict__ winner, int n_ent)
{
    int n = blockIdx.x * blockDim.x + threadIdx.x;
    if (n >= N_NODE) return;
    winner[(size_t)nb[n] * n_ent + ne[n]] = -1;
}

__global__ void k_scat1(const int* __restrict__ nb, const int* __restrict__ ne,
                        int* __restrict__ winner, int n_ent)
{
    int n = blockIdx.x * blockDim.x + threadIdx.x;
    if (n >= N_NODE) return;
    size_t slot = (size_t)nb[n] * n_ent + ne[n];
    atomicMax(&winner[slot], n);
}

__global__ void k_scat2(const float* __restrict__ h, const float* __restrict__ Wfinal,
                        const int* __restrict__ nb, const int* __restrict__ ne,
                        const int* __restrict__ winner, float* __restrict__ out, int n_ent)
{
    int n = (int)((blockIdx.x * blockDim.x + threadIdx.x) >> 5);
    int lane = threadIdx.x & 31;
    if (n >= N_NODE) return;
    float4 hv = ((const float4*)h)[(size_t)n * 32 + lane];
    float4 wv = ((const float4*)Wfinal)[lane];
    float s = hv.x * wv.x + hv.y * wv.y + hv.z * wv.z + hv.w * wv.w;
#pragma unroll
    for (int off = 16; off; off >>= 1) s += __shfl_xor_sync(0xffffffffu, s, off);
    if (lane == 0) {
        size_t slot = (size_t)nb[n] * n_ent + ne[n];
        if (winner[slot] == n) out[slot] = s;
    }
}

// ---------------- host launcher ----------------
extern "C" void kernel_launch(void* const* d_in, const int* in_sizes, int n_in,
                              void* d_out, int out_size)
{
    const float* rela     = (const float*)d_in[0];
    const float* Ws       = (const float*)d_in[1];
    const float* Wr       = (const float*)d_in[2];
    const float* Wqr_w    = (const float*)d_in[3];
    const float* Wqr_b    = (const float*)d_in[4];
    const float* Wtau     = (const float*)d_in[5];
    const float* walpha_w = (const float*)d_in[6];
    const float* walpha_b = (const float*)d_in[7];
    const float* Wh       = (const float*)d_in[8];
    const float* wt1      = (const float*)d_in[9];
    const float* bt1      = (const float*)d_in[10];
    const float* wt2      = (const float*)d_in[11];
    const float* bt2      = (const float*)d_in[12];
    const float* Wih      = (const float*)d_in[13];
    const float* Whh      = (const float*)d_in[14];
    const float* bih      = (const float*)d_in[15];
    const float* bhh      = (const float*)d_in[16];
    const float* Wfinal   = (const float*)d_in[17];
    const int*   q_rel    = (const int*)d_in[18];
    const int*   q_tau    = (const int*)d_in[19];
    const int*   e_ridx   = (const int*)d_in[20];
    const int*   e_rel    = (const int*)d_in[21];
    const int*   e_tau    = (const int*)d_in[22];
    const int*   e_sub    = (const int*)d_in[23];
    const int*   e_obj    = (const int*)d_in[24];
    const int*   nb       = (const int*)d_in[25];
    const int*   ne       = (const int*)d_in[26];

    int nq    = in_sizes[18];
    int n_ent = out_size / nq;

    float *hprev, *agg, *Hmsg;
    __half *hid16, *gi16, *gh16, *HS16, *h16, *Rattn16, *Qattn16, *Hattn16;
    int* winner;
    cudaGetSymbolAddress((void**)&hprev,   g_hprev);
    cudaGetSymbolAddress((void**)&hid16,   g_hid16);
    cudaGetSymbolAddress((void**)&agg,     g_agg);
    cudaGetSymbolAddress((void**)&gi16,    g_gi16);
    cudaGetSymbolAddress((void**)&gh16,    g_gh16);
    cudaGetSymbolAddress((void**)&HS16,    g_HS16);
    cudaGetSymbolAddress((void**)&h16,     g_h16);
    cudaGetSymbolAddress((void**)&Rattn16, g_Rattn16);
    cudaGetSymbolAddress((void**)&Qattn16, g_Qattn16);
    cudaGetSymbolAddress((void**)&Hattn16, g_Hattn16);
    cudaGetSymbolAddress((void**)&Hmsg,    g_Hmsg);
    cudaGetSymbolAddress((void**)&winner,  g_winner);

    cudaFuncSetAttribute(k_mma, cudaFuncAttributeMaxDynamicSharedMemorySize, SMEM_MMA);

    cudaMemsetAsync(hprev, 0, sizeof(float) * (size_t)N_NODE * D_DIM);

    const int mblocks = (N_NODE + 127) / 128;   // 782

    for (int l = 0; l < L_LAYERS; l++) {
        cudaMemsetAsync(agg, 0, sizeof(float) * (size_t)N_NODE * D_DIM);

        k_tab_rq<<<NREL + NQ_C, 64>>>(rela + (size_t)l * NREL * 128,
                                      Wr + (size_t)l * 64 * 128,
                                      Wqr_w + (size_t)l * 64 * 128,
                                      Wqr_b + (size_t)l * 64,
                                      q_rel, Rattn16, Qattn16);
        k_tab_delta<<<N_DELTA, 128>>>(wt1 + (size_t)l * 128, bt1 + (size_t)l * 128,
                                      wt2 + (size_t)l * 128, bt2 + (size_t)l * 128,
                                      Wtau + (size_t)l * 64 * 128, Hmsg, Hattn16);

        if (l > 0) {
            // shared-A: HS16 = fp16(hprev@Ws^T)  and  gh16 = fp16(hprev@Whh^T + bhh)
            k_mma<<<mblocks, 256, SMEM_MMA>>>(hprev, N_NODE, 0,
                                              Ws + (size_t)l * 64 * 128, nullptr,
                                              (float*)HS16, 64, 0,
                                              Whh + (size_t)l * 384 * 128,
                                              bhh + (size_t)l * 384, (float*)gh16, 384, 0,
                                              1, 1);
        }

        k_edge<<<N_EDGE / 8, 256>>>(e_sub + (size_t)l * N_EDGE, e_rel + (size_t)l * N_EDGE,
                                    e_obj + (size_t)l * N_EDGE, e_ridx + (size_t)l * N_EDGE,
                                    e_tau + (size_t)l * N_EDGE, q_tau,
                                    HS16, Rattn16, Qattn16, Hattn16, Hmsg, h16,
                                    rela + (size_t)l * NREL * 128,
                                    walpha_w + (size_t)l * 64, walpha_b + l, agg,
                                    (l == 0) ? 1 : 0);

        // hid16 = fp16(relu(agg @ Wh^T))
        k_mma<<<mblocks, 256, SMEM_MMA>>>(agg, N_NODE, 0,
                                          Wh + (size_t)l * 128 * 128, nullptr,
                                          (float*)hid16, 128, 1,
                                          nullptr, nullptr, nullptr, 0, 0, 1, 0);
        // gi16 = fp16(hid16 @ Wih^T + bih)   (A is fp16)
        k_mma<<<mblocks, 256, SMEM_MMA>>>((const float*)hid16, N_NODE, 1,
                                          Wih + (size_t)l * 384 * 128,
                                          bih + (size_t)l * 384, (float*)gi16, 384, 0,
                                          nullptr, nullptr, nullptr, 0, 0, 1, 0);
        // hprev <- GRU
        k_gru<<<(N_NODE * 32) / 256, 256>>>(gi16, (l > 0) ? gh16 : nullptr,
                                            bhh + (size_t)l * 384, hprev, h16);
    }

    cudaMemsetAsync(d_out, 0, (size_t)out_size * sizeof(float));
    k_scat0<<<(N_NODE + 255) / 256, 256>>>(nb, ne, winner, n_ent);
    k_scat1<<<(N_NODE + 255) / 256, 256>>>(nb, ne, winner, n_ent);
    k_scat2<<<(N_NODE * 32) / 256, 256>>>(hprev, Wfinal, nb, ne, winner, (float*)d_out, n_ent);
}